// round 4
// baseline (speedup 1.0000x reference)
#include <cuda_runtime.h>
#include <cstdint>
#include <cstddef>

// ---------------- problem constants ----------------
#define SP    25088          // 8*56*56
#define T_TOK 50176          // 2*SP
#define NTOK  98
#define SCALE_Q 0.125f
#define PAD_SP 33640         // 10*58*58
#define PDH    3364          // 58*58

// ---------------- scratch ----------------
__device__ float g_xln [(size_t)T_TOK*256];
__device__ float g_qkv [(size_t)T_TOK*768];
__device__ float g_attn[(size_t)T_TOK*256];
__device__ float g_xw  [(size_t)T_TOK*256];
__device__ float g_y   [(size_t)T_TOK*256];
__device__ float g_s   [(size_t)T_TOK*256];
__device__ float g_Xa  [(size_t)2*PAD_SP*128];   // zero-init padding stays zero
__device__ float g_Xb  [(size_t)2*PAD_SP*128];
__device__ float g_w2  [27*128*128];             // [tap][co][ci]

// ---------------- PTX helpers (sm_80-baseline only!) ----------------
__device__ __forceinline__ uint32_t smem_u32(const void* p) {
    uint32_t a;
    asm("{ .reg .u64 t; cvta.to.shared.u64 t, %1; cvt.u32.u64 %0, t; }" : "=r"(a) : "l"(p));
    return a;
}
__device__ __forceinline__ void cp16(uint32_t s, const void* g) {
    asm volatile("cp.async.cg.shared.global [%0], [%1], 16;" :: "r"(s), "l"(g));
}
#define CP_COMMIT() asm volatile("cp.async.commit_group;" ::: "memory")
#define CP_WAIT1()  asm volatile("cp.async.wait_group 1;"  ::: "memory")

__device__ __forceinline__ float to_tf32(float x) {
    float r;
    asm("cvt.rna.tf32.f32 %0, %1;" : "=f"(r) : "f"(x));
    return r;
}

#define MMA_TF32(c, a, b0, b1) \
    asm volatile("mma.sync.aligned.m16n8k8.row.col.f32.tf32.tf32.f32 " \
        "{%0,%1,%2,%3}, {%4,%5,%6,%7}, {%8,%9}, {%0,%1,%2,%3};" \
        : "+f"((c)[0]), "+f"((c)[1]), "+f"((c)[2]), "+f"((c)[3]) \
        : "r"(__float_as_uint((a)[0])), "r"(__float_as_uint((a)[1])), \
          "r"(__float_as_uint((a)[2])), "r"(__float_as_uint((a)[3])), \
          "r"(__float_as_uint(b0)),   "r"(__float_as_uint(b1)))

// ---------------- LN kernels ----------------
__global__ __launch_bounds__(256) void ln_in_kernel(
    const float* __restrict__ in, const float* __restrict__ w,
    const float* __restrict__ b, float* __restrict__ out)
{
    __shared__ float s[28][257];
    int bx = blockIdx.x;
    int wt = bx & 1; int tmp = bx >> 1;
    int h = tmp % 56; tmp /= 56;
    int d = tmp & 7; int bb = tmp >> 3;
    int w0 = wt * 28;
    size_t sp = ((size_t)d*56 + h)*56 + w0;
    const float* ib = in + (size_t)bb*256*SP + sp;
    for (int i = threadIdx.x; i < 28*256; i += 256) {
        int c = i / 28, ww_ = i - c*28;
        s[ww_][c] = ib[(size_t)c*SP + ww_];
    }
    __syncthreads();
    int warp = threadIdx.x >> 5, lane = threadIdx.x & 31;
    for (int tk = warp; tk < 28; tk += 8) {
        float s1 = 0.f, s2 = 0.f;
        #pragma unroll
        for (int j = 0; j < 8; j++) { float v = s[tk][lane + (j<<5)]; s1 += v; s2 += v*v; }
        #pragma unroll
        for (int o = 16; o; o >>= 1) {
            s1 += __shfl_xor_sync(0xffffffffu, s1, o);
            s2 += __shfl_xor_sync(0xffffffffu, s2, o);
        }
        float m = s1 * (1.f/256.f);
        float var = s2 * (1.f/256.f) - m*m;
        float iv = rsqrtf(var + 1e-5f);
        size_t t = (size_t)bb*SP + sp + tk;
        float* orow = out + t*256;
        #pragma unroll
        for (int j = 0; j < 8; j++) {
            int c = lane + (j<<5);
            orow[c] = (s[tk][c] - m) * iv * w[c] + b[c];
        }
    }
}

__global__ __launch_bounds__(256) void ln_row_kernel(
    const float* __restrict__ in, const float* __restrict__ w,
    const float* __restrict__ b, float* __restrict__ out)
{
    int t = blockIdx.x*8 + (threadIdx.x >> 5);
    int lane = threadIdx.x & 31;
    const float* row = in + (size_t)t*256;
    float v[8]; float s1 = 0.f, s2 = 0.f;
    #pragma unroll
    for (int j = 0; j < 8; j++) { v[j] = row[lane + (j<<5)]; s1 += v[j]; s2 += v[j]*v[j]; }
    #pragma unroll
    for (int o = 16; o; o >>= 1) {
        s1 += __shfl_xor_sync(0xffffffffu, s1, o);
        s2 += __shfl_xor_sync(0xffffffffu, s2, o);
    }
    float m = s1 * (1.f/256.f);
    float var = s2 * (1.f/256.f) - m*m;
    float iv = rsqrtf(var + 1e-5f);
    float* orow = out + (size_t)t*256;
    #pragma unroll
    for (int j = 0; j < 8; j++) {
        int c = lane + (j<<5);
        orow[c] = (v[j] - m) * iv * w[c] + b[c];
    }
}

// ---------------- SGEMM (unchanged) ----------------
__global__ __launch_bounds__(256) void gemm_tn_kernel(
    const float* __restrict__ A, const float* __restrict__ B,
    const float* __restrict__ bias, const float* __restrict__ res,
    float* __restrict__ C, int M, int N, int K)
{
    __shared__ float As[16][128];
    __shared__ float Bs[16][64];
    int bx = blockIdx.x, by = blockIdx.y;
    int tid = threadIdx.x;
    int ty = tid >> 4, tx = tid & 15;
    float4 acc[8];
    #pragma unroll
    for (int i = 0; i < 8; i++) acc[i] = make_float4(0.f,0.f,0.f,0.f);
    const int nK = K >> 4;
    for (int kb = 0; kb < nK; kb++) {
        #pragma unroll
        for (int l = 0; l < 2; l++) {
            int i = tid + (l<<8);
            int row = i >> 2, kq = (i & 3) << 2;
            float4 v = *(const float4*)(A + (size_t)(by*128 + row)*K + (kb<<4) + kq);
            As[kq+0][row]=v.x; As[kq+1][row]=v.y; As[kq+2][row]=v.z; As[kq+3][row]=v.w;
        }
        {
            int row = tid >> 2, kq = (tid & 3) << 2;
            float4 v = *(const float4*)(B + (size_t)(bx*64 + row)*K + (kb<<4) + kq);
            Bs[kq+0][row]=v.x; Bs[kq+1][row]=v.y; Bs[kq+2][row]=v.z; Bs[kq+3][row]=v.w;
        }
        __syncthreads();
        #pragma unroll
        for (int k = 0; k < 16; k++) {
            float4 a0 = *(const float4*)&As[k][ty<<3];
            float4 a1 = *(const float4*)&As[k][(ty<<3) + 4];
            float4 b0 = *(const float4*)&Bs[k][tx<<2];
            float a[8] = {a0.x,a0.y,a0.z,a0.w,a1.x,a1.y,a1.z,a1.w};
            #pragma unroll
            for (int i = 0; i < 8; i++) {
                acc[i].x += a[i]*b0.x; acc[i].y += a[i]*b0.y;
                acc[i].z += a[i]*b0.z; acc[i].w += a[i]*b0.w;
            }
        }
        __syncthreads();
    }
    float4 bv = make_float4(0.f,0.f,0.f,0.f);
    if (bias) bv = *(const float4*)(bias + (bx<<6) + (tx<<2));
    #pragma unroll
    for (int i = 0; i < 8; i++) {
        size_t m = (size_t)by*128 + (ty<<3) + i;
        size_t off = m*(size_t)N + (bx<<6) + (tx<<2);
        float4 v = acc[i];
        v.x += bv.x; v.y += bv.y; v.z += bv.z; v.w += bv.w;
        if (res) {
            float4 r = *(const float4*)(res + off);
            v.x += r.x; v.y += r.y; v.z += r.z; v.w += r.w;
        }
        *(float4*)(C + off) = v;
    }
}

// ---------------- attention (unchanged) ----------------
__global__ __launch_bounds__(128) void attn_kernel(
    const float* __restrict__ qkv, const float* __restrict__ btab,
    float* __restrict__ out, int grid_mode)
{
    extern __shared__ float sm[];
    float* ks = sm;
    float* vs = sm + NTOK*64;
    float* sc = sm + 2*NTOK*64;
    __shared__ int ts[NTOK];
    int wi = blockIdx.x, head = blockIdx.y;
    int b = wi >> 8, wd = (wi>>6)&3, wh = (wi>>3)&7, ww = wi & 7;
    int tid = threadIdx.x;
    if (tid < NTOK) {
        int pd = tid / 49; int r7 = tid - pd*49; int ph = r7 / 7, pw = r7 - ph*7;
        int d, h, w;
        if (grid_mode) { d = pd*4 + wd; h = ph*8 + wh; w = pw*8 + ww; }
        else           { d = wd*2 + pd; h = wh*7 + ph; w = ww*7 + pw; }
        ts[tid] = ((b*8 + d)*56 + h)*56 + w;
    }
    __syncthreads();
    int hoff = head << 6;
    for (int i = tid; i < NTOK*64; i += 128) {
        int r = i >> 6, c = i & 63;
        size_t base = (size_t)ts[r]*768 + hoff + c;
        ks[i] = qkv[base + 256];
        vs[i] = qkv[base + 512];
    }
    __syncthreads();
    int r = tid;
    if (r < NTOK) {
        float4 q4[16];
        const float4* qp = (const float4*)(qkv + (size_t)ts[r]*768 + hoff);
        #pragma unroll
        for (int i = 0; i < 16; i++) {
            float4 v = qp[i];
            v.x *= SCALE_Q; v.y *= SCALE_Q; v.z *= SCALE_Q; v.w *= SCALE_Q;
            q4[i] = v;
        }
        int pd_r = r / 49; int rr = r - pd_r*49; int ph_r = rr/7, pw_r = rr - ph_r*7;
        float mx = -1e30f;
        for (int m = 0; m < NTOK; m++) {
            const float4* kk = (const float4*)(ks + (m<<6));
            float s0=0.f,s1=0.f,s2=0.f,s3=0.f;
            #pragma unroll
            for (int i = 0; i < 16; i += 4) {
                float4 k0 = kk[i+0];
                s0 += q4[i+0].x*k0.x + q4[i+0].y*k0.y + q4[i+0].z*k0.z + q4[i+0].w*k0.w;
                float4 k1 = kk[i+1];
                s1 += q4[i+1].x*k1.x + q4[i+1].y*k1.y + q4[i+1].z*k1.z + q4[i+1].w*k1.w;
                float4 k2 = kk[i+2];
                s2 += q4[i+2].x*k2.x + q4[i+2].y*k2.y + q4[i+2].z*k2.z + q4[i+2].w*k2.w;
                float4 k3 = kk[i+3];
                s3 += q4[i+3].x*k3.x + q4[i+3].y*k3.y + q4[i+3].z*k3.z + q4[i+3].w*k3.w;
            }
            int pd_m = m / 49; int mm = m - pd_m*49; int ph_m = mm/7, pw_m = mm - ph_m*7;
            int rpi = ((pd_r - pd_m + 1)*13 + (ph_r - ph_m + 6))*13 + (pw_r - pw_m + 6);
            float s = (s0+s1) + (s2+s3) + btab[(rpi<<2) + head];
            sc[r*NTOK + m] = s;
            mx = fmaxf(mx, s);
        }
        float sum = 0.f;
        for (int m = 0; m < NTOK; m++) {
            float e = __expf(sc[r*NTOK + m] - mx);
            sc[r*NTOK + m] = e; sum += e;
        }
        float inv = 1.f / sum;
        float4 a4[16];
        #pragma unroll
        for (int i = 0; i < 16; i++) a4[i] = make_float4(0.f,0.f,0.f,0.f);
        for (int m = 0; m < NTOK; m++) {
            float a = sc[r*NTOK + m] * inv;
            const float4* vv = (const float4*)(vs + (m<<6));
            #pragma unroll
            for (int i = 0; i < 16; i++) {
                float4 v = vv[i];
                a4[i].x += a*v.x; a4[i].y += a*v.y; a4[i].z += a*v.z; a4[i].w += a*v.w;
            }
        }
        float4* op = (float4*)(out + (size_t)ts[r]*256 + hoff);
        #pragma unroll
        for (int i = 0; i < 16; i++) op[i] = a4[i];
    }
}

// ---------------- s = input + y; also emit padded token-major s2 -> Xa (tf32) ---------
__global__ __launch_bounds__(256) void add_s_kernel(
    const float* __restrict__ in, const float* __restrict__ y,
    float* __restrict__ s, float* __restrict__ Xa)
{
    __shared__ float sm[256][33];
    int b0 = blockIdx.x * 32;
    for (int i = threadIdx.x; i < 32*256; i += 256) {
        int tk = i >> 8, c = i & 255;
        sm[c][tk] = y[(size_t)(b0 + tk)*256 + c];
    }
    __syncthreads();
    int b = b0 / SP; int sp0 = b0 % SP;
    for (int i = threadIdx.x; i < 32*256; i += 256) {
        int c = i >> 5, k = i & 31;
        size_t gi = ((size_t)b*256 + c)*SP + sp0 + k;
        float v = in[gi] + sm[c][k];
        s[gi] = v;
        sm[c][k] = v;
    }
    __syncthreads();
    for (int i = threadIdx.x; i < 32*128; i += 256) {
        int tok = i >> 7, ci = i & 127;
        int sp = sp0 + tok;
        int d = sp / 3136; int r = sp - d*3136; int h = r / 56, w = r - h*56;
        int pad = (d+1)*PDH + (h+1)*58 + (w+1);
        Xa[((size_t)b*PAD_SP + pad)*128 + ci] = to_tf32(sm[128+ci][tok]);
    }
}

// ---------------- conv weight transform: [co][ci][tap] -> [tap][co][ci] (tf32) --------
__global__ void wt2_kernel(const float* __restrict__ w, float* __restrict__ o)
{
    int i = blockIdx.x*256 + threadIdx.x;
    if (i >= 27*128*128) return;
    int ci = i & 127; int r = i >> 7; int co = r & 127; int tap = r >> 7;
    o[i] = to_tf32(w[(co*128 + ci)*27 + tap]);
}

// ---------------- tf32 mma.sync implicit-GEMM conv ----------------
// block: M=128 positions x N=128 co; K = 27 taps x 128 ci staged in 108 chunks of 32.
// 8 warps = 4(M) x 2(N); warp tile 32x64 via m16n8k8; cp.async double buffer.
__global__ __launch_bounds__(256) void conv_mma_kernel(
    const float* __restrict__ Xin, const float* __restrict__ w2,
    const float* __restrict__ bias, const float* __restrict__ res,
    float* __restrict__ outN, float* __restrict__ outX, int leaky)
{
    extern __shared__ __align__(16) float dsm[];   // 2 stages x 8192 floats; epilogue Cbuf 128x132
    __shared__ float sbias[128];

    const int tid  = threadIdx.x;
    const int lane = tid & 31;
    const int wid  = tid >> 5;
    const int wm   = wid & 3;          // M tile (x32)
    const int wn   = wid >> 2;         // N tile (x64)
    const int r0   = lane >> 2;
    const int c0   = lane & 3;
    const int bx   = blockIdx.x;
    const int b    = bx / 196;
    const int spb  = (bx % 196) * 128;

    if (tid < 128) sbias[tid] = bias[tid];

    // staging assignment: thread copies row mrow, quads [q0, q0+4)
    const int mrow = tid >> 1;
    const int q0   = (tid & 1) * 4;
    int sp_c = spb + mrow;
    int d_c = sp_c / 3136; int r_c = sp_c - d_c*3136; int h_c = r_c / 56, w_c = r_c - h_c*56;
    const int padrow = d_c*PDH + h_c*58 + w_c;
    const float* XinB = Xin + (size_t)b * PAD_SP * 128;
    const uint32_t smem_base = smem_u32(dsm);
    const uint32_t arow = smem_base + (uint32_t)mrow*128u;

    float c[2][8][4];
    #pragma unroll
    for (int t = 0; t < 2; t++)
        #pragma unroll
        for (int t2 = 0; t2 < 8; t2++)
            #pragma unroll
            for (int j = 0; j < 4; j++) c[t][t2][j] = 0.f;

    const int NIT = 108;

    // stage loader
    auto load_stage = [&](int k) {
        int tap = k >> 2, kq = k & 3;
        int kd = tap / 9; int rem = tap - kd*9; int kh = rem / 3, kw = rem - kh*3;
        int toff = kd*PDH + kh*58 + kw;
        uint32_t sA = arow + (uint32_t)(k & 1) * 32768u;
        uint32_t sB = sA + 16384u;
        const float* ga = XinB + (size_t)(padrow + toff)*128 + kq*32;
        const float* gb = w2 + ((size_t)tap*128 + mrow)*128 + kq*32;
        #pragma unroll
        for (int q = q0; q < q0 + 4; q++) {
            uint32_t pq = (uint32_t)(q ^ (mrow & 7)) * 16u;
            cp16(sA + pq, ga + q*4);
            cp16(sB + pq, gb + q*4);
        }
    };

    load_stage(0);
    CP_COMMIT();

    for (int k = 0; k < NIT; k++) {
        if (k + 1 < NIT) load_stage(k + 1);
        CP_COMMIT();
        CP_WAIT1();
        __syncthreads();

        const float* As = dsm + (k & 1) * 8192;
        const float* Bs = As + 4096;
        #pragma unroll
        for (int kk = 0; kk < 4; kk++) {
            int k1 = kk*8 + c0, k2 = k1 + 4;
            float a[2][4];
            #pragma unroll
            for (int t = 0; t < 2; t++) {
                int rm  = wm*32 + t*16 + r0;     // rm&7 == r0
                int xm  = r0 << 2;
                a[t][0] = As[rm*32       + (k1 ^ xm)];
                a[t][1] = As[(rm+8)*32   + (k1 ^ xm)];
                a[t][2] = As[rm*32       + (k2 ^ xm)];
                a[t][3] = As[(rm+8)*32   + (k2 ^ xm)];
            }
            #pragma unroll
            for (int t2 = 0; t2 < 8; t2++) {
                int n  = wn*64 + t2*8 + r0;      // n&7 == r0
                int xn = r0 << 2;
                float b0 = Bs[n*32 + (k1 ^ xn)];
                float b1 = Bs[n*32 + (k2 ^ xn)];
                MMA_TF32(c[0][t2], a[0], b0, b1);
                MMA_TF32(c[1][t2], a[1], b0, b1);
            }
        }
        __syncthreads();
    }

    // ---------------- epilogue ----------------
    float* Cb = dsm;                               // 128 x 132
    #pragma unroll
    for (int t = 0; t < 2; t++) {
        int row = wm*32 + t*16 + r0;
        #pragma unroll
        for (int t2 = 0; t2 < 8; t2++) {
            int col = wn*64 + t2*8 + (c0 << 1);
            float b0s = sbias[col], b1s = sbias[col+1];
            float v0 = c[t][t2][0] + b0s;
            float v1 = c[t][t2][1] + b1s;
            float v2 = c[t][t2][2] + b0s;
            float v3 = c[t][t2][3] + b1s;
            if (leaky) {
                v0 = (v0 >= 0.f) ? v0 : 0.01f*v0;
                v1 = (v1 >= 0.f) ? v1 : 0.01f*v1;
                v2 = (v2 >= 0.f) ? v2 : 0.01f*v2;
                v3 = (v3 >= 0.f) ? v3 : 0.01f*v3;
            }
            Cb[row*132 + col]       = v0;
            Cb[row*132 + col + 1]   = v1;
            Cb[(row+8)*132 + col]   = v2;
            Cb[(row+8)*132 + col+1] = v3;
        }
    }
    __syncthreads();

    if (res) {
        int co = tid >> 1, mh = (tid & 1) << 6;
        const float* rp = res + (size_t)b*256*SP + (size_t)co*SP + spb + mh;
        #pragma unroll
        for (int j4 = 0; j4 < 16; j4++) {
            float4 r4 = *(const float4*)(rp + j4*4);
            Cb[(mh + j4*4 + 0)*132 + co] += r4.x;
            Cb[(mh + j4*4 + 1)*132 + co] += r4.y;
            Cb[(mh + j4*4 + 2)*132 + co] += r4.z;
            Cb[(mh + j4*4 + 3)*132 + co] += r4.w;
        }
        __syncthreads();
    }

    if (outX) {
        int m = tid >> 1, ch = (tid & 1) << 6;
        int sp = spb + m; int d = sp / 3136; int r = sp - d*3136; int h = r / 56, w = r - h*56;
        size_t po = (size_t)(d+1)*PDH + (size_t)(h+1)*58 + (w+1);
        float* xp = outX + ((size_t)b*PAD_SP + po)*128 + ch;
        #pragma unroll
        for (int j4 = 0; j4 < 16; j4++) {
            float4 v = *(const float4*)&Cb[m*132 + ch + j4*4];
            v.x = to_tf32(v.x); v.y = to_tf32(v.y); v.z = to_tf32(v.z); v.w = to_tf32(v.w);
            *(float4*)(xp + j4*4) = v;
        }
    }
    if (outN) {
        int co = tid >> 1, mh = (tid & 1) << 6;
        float* op = outN + (size_t)b*256*SP + (size_t)co*SP + spb + mh;
        #pragma unroll
        for (int j4 = 0; j4 < 16; j4++) {
            float4 o;
            o.x = Cb[(mh + j4*4 + 0)*132 + co];
            o.y = Cb[(mh + j4*4 + 1)*132 + co];
            o.z = Cb[(mh + j4*4 + 2)*132 + co];
            o.w = Cb[(mh + j4*4 + 3)*132 + co];
            *(float4*)(op + j4*4) = o;
        }
    }
}

// ---------------- launcher ----------------
extern "C" void kernel_launch(void* const* d_in, const int* in_sizes, int n_in,
                              void* d_out, int out_size)
{
    (void)in_sizes; (void)n_in; (void)out_size;
    const float* input  = (const float*)d_in[0];
    const float* n1w    = (const float*)d_in[1];
    const float* n1b    = (const float*)d_in[2];
    const float* n2w    = (const float*)d_in[3];
    const float* n2b    = (const float*)d_in[4];
    const float* wqkv   = (const float*)d_in[5];
    const float* wprojw = (const float*)d_in[6];
    const float* wprojb = (const float*)d_in[7];
    const float* wbias  = (const float*)d_in[8];
    const float* gqkv   = (const float*)d_in[9];
    const float* gprojw = (const float*)d_in[10];
    const float* gprojb = (const float*)d_in[11];
    const float* gbias  = (const float*)d_in[12];
    const float* f1c1w  = (const float*)d_in[13];
    const float* f1c1b  = (const float*)d_in[14];
    const float* f1c2w  = (const float*)d_in[15];
    const float* f1c2b  = (const float*)d_in[16];
    const float* g1c1w  = (const float*)d_in[17];
    const float* g1c1b  = (const float*)d_in[18];
    const float* g1c2w  = (const float*)d_in[19];
    const float* g1c2b  = (const float*)d_in[20];
    float* out = (float*)d_out;

    float *xln, *qkvb, *attn, *xw, *y, *s, *Xa, *Xb, *w2;
    cudaGetSymbolAddress((void**)&xln,  g_xln);
    cudaGetSymbolAddress((void**)&qkvb, g_qkv);
    cudaGetSymbolAddress((void**)&attn, g_attn);
    cudaGetSymbolAddress((void**)&xw,   g_xw);
    cudaGetSymbolAddress((void**)&y,    g_y);
    cudaGetSymbolAddress((void**)&s,    g_s);
    cudaGetSymbolAddress((void**)&Xa,   g_Xa);
    cudaGetSymbolAddress((void**)&Xb,   g_Xb);
    cudaGetSymbolAddress((void**)&w2,   g_w2);

    const int ATTN_SMEM = (2*NTOK*64 + NTOK*NTOK) * (int)sizeof(float);
    cudaFuncSetAttribute(attn_kernel, cudaFuncAttributeMaxDynamicSharedMemorySize, ATTN_SMEM);
    const int CONV_SMEM = 128*132*4;   // 67584 B (>= 2*32768 stage bytes)
    cudaFuncSetAttribute(conv_mma_kernel, cudaFuncAttributeMaxDynamicSharedMemorySize, CONV_SMEM);

    ln_in_kernel<<<1792, 256>>>(input, n1w, n1b, xln);
    gemm_tn_kernel<<<dim3(12, 392), 256>>>(xln, wqkv, nullptr, nullptr, qkvb, T_TOK, 768, 256);
    attn_kernel<<<dim3(512, 4), 128, ATTN_SMEM>>>(qkvb, wbias, attn, 0);
    gemm_tn_kernel<<<dim3(4, 392), 256>>>(attn, wprojw, wprojb, nullptr, xw, T_TOK, 256, 256);
    ln_row_kernel<<<6272, 256>>>(xw, n2w, n2b, xln);
    gemm_tn_kernel<<<dim3(12, 392), 256>>>(xln, gqkv, nullptr, nullptr, qkvb, T_TOK, 768, 256);
    attn_kernel<<<dim3(512, 4), 128, ATTN_SMEM>>>(qkvb, gbias, attn, 1);
    gemm_tn_kernel<<<dim3(4, 392), 256>>>(attn, gprojw, gprojb, xw, y, T_TOK, 256, 256);
    add_s_kernel<<<1568, 256>>>(input, y, s, Xa);

    // conv1: t1 = leaky(conv(s2, f1c1)+b)       Xa -> Xb
    wt2_kernel<<<1728, 256>>>(f1c1w, w2);
    conv_mma_kernel<<<392, 256, CONV_SMEM>>>(Xa, w2, f1c1b, nullptr, nullptr, Xb, 1);
    // conv2: y1 = s1 + conv(t1, f1c2)+b         Xb -> out[0:128] + Xa
    wt2_kernel<<<1728, 256>>>(f1c2w, w2);
    conv_mma_kernel<<<392, 256, CONV_SMEM>>>(Xb, w2, f1c2b, s, out, Xa, 0);
    // conv3: t2 = leaky(conv(y1, g1c1)+b)       Xa -> Xb
    wt2_kernel<<<1728, 256>>>(g1c1w, w2);
    conv_mma_kernel<<<392, 256, CONV_SMEM>>>(Xa, w2, g1c1b, nullptr, nullptr, Xb, 1);
    // conv4: y2 = s2 + conv(t2, g1c2)+b         Xb -> out[128:256]
    wt2_kernel<<<1728, 256>>>(g1c2w, w2);
    conv_mma_kernel<<<392, 256, CONV_SMEM>>>(Xb, w2, g1c2b, s + (size_t)128*SP,
                                             out + (size_t)128*SP, nullptr, 0);
}

// round 5
// speedup vs baseline: 2.0020x; 2.0020x over previous
#include <cuda_runtime.h>
#include <cuda_fp16.h>
#include <cstdint>
#include <cstddef>

// ---------------- problem constants ----------------
#define SP    25088          // 8*56*56
#define T_TOK 50176          // 2*SP
#define NTOK  98
#define SCALE_Q 0.125f
#define PAD_SP 33640         // 10*58*58
#define PDH    3364          // 58*58

// ---------------- scratch ----------------
__device__ __half g_xh  [(size_t)T_TOK*256];
__device__ __half g_qkvh[(size_t)T_TOK*768];
__device__ __half g_atnh[(size_t)T_TOK*256];
__device__ float  g_xw  [(size_t)T_TOK*256];
__device__ float  g_y   [(size_t)T_TOK*256];
__device__ float  g_s   [(size_t)T_TOK*256];
__device__ __half g_Xa  [(size_t)2*PAD_SP*128];   // zero-init padding stays zero
__device__ __half g_Xb  [(size_t)2*PAD_SP*128];
__device__ __half g_w2h [27*128*128];             // [tap][co][ci]
__device__ __half g_wqkvh[768*256];
__device__ __half g_gqkvh[768*256];
__device__ __half g_wprjh[256*256];
__device__ __half g_gprjh[256*256];

// ---------------- PTX helpers (sm_80-baseline only) ----------------
__device__ __forceinline__ uint32_t smem_u32(const void* p) {
    uint32_t a;
    asm("{ .reg .u64 t; cvta.to.shared.u64 t, %1; cvt.u32.u64 %0, t; }" : "=r"(a) : "l"(p));
    return a;
}
__device__ __forceinline__ void cp16(uint32_t s, const void* g) {
    asm volatile("cp.async.cg.shared.global [%0], [%1], 16;" :: "r"(s), "l"(g));
}
#define CP_COMMIT() asm volatile("cp.async.commit_group;" ::: "memory")
#define CP_WAIT1()  asm volatile("cp.async.wait_group 1;"  ::: "memory")

__device__ __forceinline__ void ldsm4(uint32_t* r, uint32_t a) {
    asm volatile("ldmatrix.sync.aligned.m8n8.x4.shared.b16 {%0,%1,%2,%3}, [%4];"
        : "=r"(r[0]), "=r"(r[1]), "=r"(r[2]), "=r"(r[3]) : "r"(a));
}
#define MMA_F16(c, a, b0, b1) \
    asm volatile("mma.sync.aligned.m16n8k16.row.col.f32.f16.f16.f32 " \
        "{%0,%1,%2,%3}, {%4,%5,%6,%7}, {%8,%9}, {%0,%1,%2,%3};" \
        : "+f"((c)[0]), "+f"((c)[1]), "+f"((c)[2]), "+f"((c)[3]) \
        : "r"((a)[0]), "r"((a)[1]), "r"((a)[2]), "r"((a)[3]), "r"(b0), "r"(b1))

// ---------------- fp32 -> fp16 convert ----------------
__global__ void f2h_kernel(const float* __restrict__ src, __half* __restrict__ dst, int n)
{
    int i = blockIdx.x*256 + threadIdx.x;
    if (i < n) dst[i] = __float2half_rn(src[i]);
}

// ---------------- LN kernels (output half) ----------------
__global__ __launch_bounds__(256) void ln_in_kernel(
    const float* __restrict__ in, const float* __restrict__ w,
    const float* __restrict__ b, __half* __restrict__ out)
{
    __shared__ float s[28][257];
    int bx = blockIdx.x;
    int wt = bx & 1; int tmp = bx >> 1;
    int h = tmp % 56; tmp /= 56;
    int d = tmp & 7; int bb = tmp >> 3;
    int w0 = wt * 28;
    size_t sp = ((size_t)d*56 + h)*56 + w0;
    const float* ib = in + (size_t)bb*256*SP + sp;
    for (int i = threadIdx.x; i < 28*256; i += 256) {
        int c = i / 28, ww_ = i - c*28;
        s[ww_][c] = ib[(size_t)c*SP + ww_];
    }
    __syncthreads();
    int warp = threadIdx.x >> 5, lane = threadIdx.x & 31;
    for (int tk = warp; tk < 28; tk += 8) {
        float s1 = 0.f, s2 = 0.f;
        #pragma unroll
        for (int j = 0; j < 8; j++) { float v = s[tk][lane + (j<<5)]; s1 += v; s2 += v*v; }
        #pragma unroll
        for (int o = 16; o; o >>= 1) {
            s1 += __shfl_xor_sync(0xffffffffu, s1, o);
            s2 += __shfl_xor_sync(0xffffffffu, s2, o);
        }
        float m = s1 * (1.f/256.f);
        float var = s2 * (1.f/256.f) - m*m;
        float iv = rsqrtf(var + 1e-5f);
        size_t t = (size_t)bb*SP + sp + tk;
        __half* orow = out + t*256;
        #pragma unroll
        for (int j = 0; j < 8; j++) {
            int c = lane + (j<<5);
            orow[c] = __float2half_rn((s[tk][c] - m) * iv * w[c] + b[c]);
        }
    }
}

__global__ __launch_bounds__(256) void ln_row_kernel(
    const float* __restrict__ in, const float* __restrict__ w,
    const float* __restrict__ b, __half* __restrict__ out)
{
    int t = blockIdx.x*8 + (threadIdx.x >> 5);
    int lane = threadIdx.x & 31;
    const float* row = in + (size_t)t*256;
    float v[8]; float s1 = 0.f, s2 = 0.f;
    #pragma unroll
    for (int j = 0; j < 8; j++) { v[j] = row[lane + (j<<5)]; s1 += v[j]; s2 += v[j]*v[j]; }
    #pragma unroll
    for (int o = 16; o; o >>= 1) {
        s1 += __shfl_xor_sync(0xffffffffu, s1, o);
        s2 += __shfl_xor_sync(0xffffffffu, s2, o);
    }
    float m = s1 * (1.f/256.f);
    float var = s2 * (1.f/256.f) - m*m;
    float iv = rsqrtf(var + 1e-5f);
    __half* orow = out + (size_t)t*256;
    #pragma unroll
    for (int j = 0; j < 8; j++) {
        int c = lane + (j<<5);
        orow[c] = __float2half_rn((v[j] - m) * iv * w[c] + b[c]);
    }
}

// ---------------- shared warp-MMA stage: 128x128 tile, BK=64 ----------------
// smem tile layout: 128 rows x 64 halves (128B, 8 chunks of 16B), chunk swizzle c^(row&7)
// 8 warps = 4(M) x 2(N); warp tile 32x64.
struct FragCtx {
    uint32_t aoff;    // A row byte offset (lane)
    uint32_t boff;    // B row byte offset (lane, group 0)
    uint32_t axor[4]; // per kk: A chunk xor term <<4
    uint32_t bxor[4]; // per kk: B chunk xor term <<4
};
__device__ __forceinline__ FragCtx make_frag_ctx(int lane, int wm, int wn) {
    FragCtx f;
    int l7 = lane & 7;
    f.aoff = (uint32_t)((wm*32 + ((lane>>3)&1)*8 + l7) * 128);
    f.boff = (uint32_t)((wn*64 + ((lane>>4)&1)*8 + l7) * 128);
    #pragma unroll
    for (int kk = 0; kk < 4; kk++) {
        f.axor[kk] = (uint32_t)(((2*kk + (lane>>4)) ^ l7) << 4);
        f.bxor[kk] = (uint32_t)(((2*kk + ((lane>>3)&1)) ^ l7) << 4);
    }
    return f;
}
__device__ __forceinline__ void mma_stage(uint32_t Ab, uint32_t Bb,
                                          const FragCtx& f, float c[2][8][4])
{
    #pragma unroll
    for (int kk = 0; kk < 4; kk++) {
        uint32_t a0[4], a1[4];
        ldsm4(a0, Ab + f.aoff + f.axor[kk]);
        ldsm4(a1, Ab + f.aoff + 2048u + f.axor[kk]);
        #pragma unroll
        for (int g = 0; g < 4; g++) {
            uint32_t bb[4];
            ldsm4(bb, Bb + f.boff + (uint32_t)g*2048u + f.bxor[kk]);
            MMA_F16(c[0][2*g],   a0, bb[0], bb[1]);
            MMA_F16(c[1][2*g],   a1, bb[0], bb[1]);
            MMA_F16(c[0][2*g+1], a0, bb[2], bb[3]);
            MMA_F16(c[1][2*g+1], a1, bb[2], bb[3]);
        }
    }
}

// ---------------- fp16 GEMM: C[M,N] = A[M,256] @ B[N,256]^T (+bias)(+res) --------------
// grid (N/128, 392); OUTHALF: 1 -> C half, 0 -> C float
template<int OUTHALF>
__global__ __launch_bounds__(256, 2) void hgemm_kernel(
    const __half* __restrict__ A, const __half* __restrict__ B,
    const float* __restrict__ bias, const float* __restrict__ res,
    void* __restrict__ Cout, int N)
{
    extern __shared__ __align__(16) char dsm[];
    __shared__ float sbias[128];
    const int tid = threadIdx.x, lane = tid & 31, wid = tid >> 5;
    const int wm = wid & 3, wn = wid >> 2;
    const int bx = blockIdx.x, by = blockIdx.y;

    sbias[tid >> 1] = 0.f;  // covered twice; then real load
    if (bias && tid < 128) sbias[tid] = bias[bx*128 + tid];
    else if (tid < 128 && !bias) sbias[tid] = 0.f;

    const int mrow = tid >> 1;
    const int q0 = (tid & 1) * 4;
    const __half* asrc = A + ((size_t)(by*128 + mrow))*256;
    const __half* bsrc = B + ((size_t)(bx*128 + mrow))*256;
    const uint32_t sb = smem_u32(dsm);
    const uint32_t dst = sb + (uint32_t)mrow*128u;
    FragCtx f = make_frag_ctx(lane, wm, wn);

    float c[2][8][4];
    #pragma unroll
    for (int t = 0; t < 2; t++)
        #pragma unroll
        for (int j = 0; j < 8; j++)
            #pragma unroll
            for (int q = 0; q < 4; q++) c[t][j][q] = 0.f;

    auto load_st = [&](int s) {
        uint32_t base = (uint32_t)(s % 3) * 32768u;
        #pragma unroll
        for (int q = q0; q < q0 + 4; q++) {
            uint32_t sw = (uint32_t)((q ^ (mrow & 7)) << 4);
            cp16(dst + base + sw, asrc + s*64 + q*8);
            cp16(dst + base + 16384u + sw, bsrc + s*64 + q*8);
        }
    };
    load_st(0); CP_COMMIT();
    load_st(1); CP_COMMIT();
    #pragma unroll
    for (int k = 0; k < 4; k++) {
        CP_WAIT1();
        __syncthreads();
        if (k + 2 < 4) load_st(k + 2);
        CP_COMMIT();
        uint32_t Ab = sb + (uint32_t)(k % 3)*32768u;
        mma_stage(Ab, Ab + 16384u, f, c);
    }
    __syncthreads();

    // epilogue via Cbuf
    float* Cb = (float*)dsm;   // 128 x 132
    const int r0 = lane >> 2, c0 = lane & 3;
    #pragma unroll
    for (int t = 0; t < 2; t++) {
        int row = wm*32 + t*16 + r0;
        #pragma unroll
        for (int t2 = 0; t2 < 8; t2++) {
            int col = wn*64 + t2*8 + (c0 << 1);
            Cb[row*132 + col]       = c[t][t2][0] + sbias[col];
            Cb[row*132 + col + 1]   = c[t][t2][1] + sbias[col+1];
            Cb[(row+8)*132 + col]   = c[t][t2][2] + sbias[col];
            Cb[(row+8)*132 + col+1] = c[t][t2][3] + sbias[col+1];
        }
    }
    __syncthreads();

    const int m = tid >> 1, ch = (tid & 1) << 6;
    size_t goff = ((size_t)(by*128 + m))*N + bx*128 + ch;
    if (OUTHALF) {
        __half* Ch = (__half*)Cout;
        #pragma unroll
        for (int j8 = 0; j8 < 8; j8++) {
            uint4 u;
            const float* p = &Cb[m*132 + ch + j8*8];
            u.x = __half2half2(__float2half_rn(0.f)).x; // placeholder overwritten below
            __half2 h0 = __floats2half2_rn(p[0], p[1]);
            __half2 h1 = __floats2half2_rn(p[2], p[3]);
            __half2 h2 = __floats2half2_rn(p[4], p[5]);
            __half2 h3 = __floats2half2_rn(p[6], p[7]);
            u.x = *(uint32_t*)&h0; u.y = *(uint32_t*)&h1;
            u.z = *(uint32_t*)&h2; u.w = *(uint32_t*)&h3;
            *(uint4*)(Ch + goff + j8*8) = u;
        }
    } else {
        float* Cf = (float*)Cout;
        #pragma unroll
        for (int j4 = 0; j4 < 16; j4++) {
            float4 v = *(const float4*)&Cb[m*132 + ch + j4*4];
            if (res) {
                float4 r = *(const float4*)(res + goff + j4*4);
                v.x += r.x; v.y += r.y; v.z += r.z; v.w += r.w;
            }
            *(float4*)(Cf + goff + j4*4) = v;
        }
    }
}

// ---------------- attention (half in/out, fp32 math) ----------------
__global__ __launch_bounds__(128) void attn_kernel(
    const __half* __restrict__ qkv, const float* __restrict__ btab,
    __half* __restrict__ out, int grid_mode)
{
    extern __shared__ float sm[];
    float* ks = sm;
    float* vs = sm + NTOK*64;
    float* sc = sm + 2*NTOK*64;
    __shared__ int ts[NTOK];
    int wi = blockIdx.x, head = blockIdx.y;
    int b = wi >> 8, wd = (wi>>6)&3, wh = (wi>>3)&7, ww = wi & 7;
    int tid = threadIdx.x;
    if (tid < NTOK) {
        int pd = tid / 49; int r7 = tid - pd*49; int ph = r7 / 7, pw = r7 - ph*7;
        int d, h, w;
        if (grid_mode) { d = pd*4 + wd; h = ph*8 + wh; w = pw*8 + ww; }
        else           { d = wd*2 + pd; h = wh*7 + ph; w = ww*7 + pw; }
        ts[tid] = ((b*8 + d)*56 + h)*56 + w;
    }
    __syncthreads();
    int hoff = head << 6;
    for (int i = tid; i < NTOK*64; i += 128) {
        int r = i >> 6, c = i & 63;
        size_t base = (size_t)ts[r]*768 + hoff + c;
        ks[i] = __half2float(qkv[base + 256]);
        vs[i] = __half2float(qkv[base + 512]);
    }
    __syncthreads();
    int r = tid;
    if (r < NTOK) {
        float4 q4[16];
        const __half2* qp = (const __half2*)(qkv + (size_t)ts[r]*768 + hoff);
        #pragma unroll
        for (int i = 0; i < 16; i++) {
            float2 f0 = __half22float2(qp[2*i]);
            float2 f1 = __half22float2(qp[2*i+1]);
            q4[i] = make_float4(f0.x*SCALE_Q, f0.y*SCALE_Q, f1.x*SCALE_Q, f1.y*SCALE_Q);
        }
        int pd_r = r / 49; int rr = r - pd_r*49; int ph_r = rr/7, pw_r = rr - ph_r*7;
        float mx = -1e30f;
        for (int m = 0; m < NTOK; m++) {
            const float4* kk = (const float4*)(ks + (m<<6));
            float s0=0.f,s1=0.f,s2=0.f,s3=0.f;
            #pragma unroll
            for (int i = 0; i < 16; i += 4) {
                float4 k0 = kk[i+0];
                s0 += q4[i+0].x*k0.x + q4[i+0].y*k0.y + q4[i+0].z*k0.z + q4[i+0].w*k0.w;
                float4 k1 = kk[i+1];
                s1 += q4[i+1].x*k1.x + q4[i+1].y*k1.y + q4[i+1].z*k1.z + q4[i+1].w*k1.w;
                float4 k2 = kk[i+2];
                s2 += q4[i+2].x*k2.x + q4[i+2].y*k2.y + q4[i+2].z*k2.z + q4[i+2].w*k2.w;
                float4 k3 = kk[i+3];
                s3 += q4[i+3].x*k3.x + q4[i+3].y*k3.y + q4[i+3].z*k3.z + q4[i+3].w*k3.w;
            }
            int pd_m = m / 49; int mm = m - pd_m*49; int ph_m = mm/7, pw_m = mm - ph_m*7;
            int rpi = ((pd_r - pd_m + 1)*13 + (ph_r - ph_m + 6))*13 + (pw_r - pw_m + 6);
            float s = (s0+s1) + (s2+s3) + btab[(rpi<<2) + head];
            sc[r*NTOK + m] = s;
            mx = fmaxf(mx, s);
        }
        float sum = 0.f;
        for (int m = 0; m < NTOK; m++) {
            float e = __expf(sc[r*NTOK + m] - mx);
            sc[r*NTOK + m] = e; sum += e;
        }
        float inv = 1.f / sum;
        float4 a4[16];
        #pragma unroll
        for (int i = 0; i < 16; i++) a4[i] = make_float4(0.f,0.f,0.f,0.f);
        for (int m = 0; m < NTOK; m++) {
            float a = sc[r*NTOK + m] * inv;
            const float4* vv = (const float4*)(vs + (m<<6));
            #pragma unroll
            for (int i = 0; i < 16; i++) {
                float4 v = vv[i];
                a4[i].x += a*v.x; a4[i].y += a*v.y; a4[i].z += a*v.z; a4[i].w += a*v.w;
            }
        }
        __half2* op = (__half2*)(out + (size_t)ts[r]*256 + hoff);
        #pragma unroll
        for (int i = 0; i < 16; i++) {
            op[2*i]   = __floats2half2_rn(a4[i].x, a4[i].y);
            op[2*i+1] = __floats2half2_rn(a4[i].z, a4[i].w);
        }
    }
}

// ---------------- s = input + y (fp32 NCDHW) + padded half s2 -> Xa ----------------
__global__ __launch_bounds__(256) void add_s_kernel(
    const float* __restrict__ in, const float* __restrict__ y,
    float* __restrict__ s, __half* __restrict__ Xa)
{
    __shared__ float sm[256][33];
    int b0 = blockIdx.x * 32;
    for (int i = threadIdx.x; i < 32*256; i += 256) {
        int tk = i >> 8, c = i & 255;
        sm[c][tk] = y[(size_t)(b0 + tk)*256 + c];
    }
    __syncthreads();
    int b = b0 / SP; int sp0 = b0 % SP;
    for (int i = threadIdx.x; i < 32*256; i += 256) {
        int c = i >> 5, k = i & 31;
        size_t gi = ((size_t)b*256 + c)*SP + sp0 + k;
        float v = in[gi] + sm[c][k];
        s[gi] = v;
        sm[c][k] = v;
    }
    __syncthreads();
    for (int i = threadIdx.x; i < 32*128; i += 256) {
        int tok = i >> 7, ci = i & 127;
        int sp = sp0 + tok;
        int d = sp / 3136; int r = sp - d*3136; int h = r / 56, w = r - h*56;
        int pad = (d+1)*PDH + (h+1)*58 + (w+1);
        Xa[((size_t)b*PAD_SP + pad)*128 + ci] = __float2half_rn(sm[128+ci][tok]);
    }
}

// ---------------- conv weight transform: [co][ci][tap] -> [tap][co][ci] half ----------
__global__ void wt2_kernel(const float* __restrict__ w, __half* __restrict__ o)
{
    int i = blockIdx.x*256 + threadIdx.x;
    if (i >= 27*128*128) return;
    int ci = i & 127; int r = i >> 7; int co = r & 127; int tap = r >> 7;
    o[i] = __float2half_rn(w[(co*128 + ci)*27 + tap]);
}

// ---------------- fp16 implicit-GEMM conv ----------------
// M=128 positions x N=128 co; K = 27 taps x 128 ci as 54 stages of 64.
__global__ __launch_bounds__(256, 2) void conv_mma_kernel(
    const __half* __restrict__ Xin, const __half* __restrict__ w2,
    const float* __restrict__ bias, const float* __restrict__ res,
    float* __restrict__ outN, __half* __restrict__ outX, int leaky)
{
    extern __shared__ __align__(16) char dsm[];
    __shared__ float sbias[128];

    const int tid = threadIdx.x, lane = tid & 31, wid = tid >> 5;
    const int wm = wid & 3, wn = wid >> 2;
    const int bx = blockIdx.x;
    const int b = bx / 196;
    const int spb = (bx % 196) * 128;

    if (tid < 128) sbias[tid] = bias[tid];

    const int mrow = tid >> 1;
    const int q0 = (tid & 1) * 4;
    int sp_c = spb + mrow;
    int d_c = sp_c / 3136; int r_c = sp_c - d_c*3136; int h_c = r_c / 56, w_c = r_c - h_c*56;
    const int padrow = d_c*PDH + h_c*58 + w_c;
    const __half* XinB = Xin + (size_t)b * PAD_SP * 128;
    const uint32_t sb = smem_u32(dsm);
    const uint32_t dst = sb + (uint32_t)mrow*128u;
    FragCtx f = make_frag_ctx(lane, wm, wn);

    float c[2][8][4];
    #pragma unroll
    for (int t = 0; t < 2; t++)
        #pragma unroll
        for (int j = 0; j < 8; j++)
            #pragma unroll
            for (int q = 0; q < 4; q++) c[t][j][q] = 0.f;

    const int NST = 54;
    auto load_st = [&](int s) {
        int tap = s >> 1, kh64 = (s & 1) * 64;
        int kd = tap / 9; int rem = tap - kd*9; int kh = rem / 3, kw = rem - kh*3;
        int toff = kd*PDH + kh*58 + kw;
        uint32_t base = (uint32_t)(s % 3) * 32768u;
        const __half* ga = XinB + (size_t)(padrow + toff)*128 + kh64;
        const __half* gb = w2 + ((size_t)tap*128 + mrow)*128 + kh64;
        #pragma unroll
        for (int q = q0; q < q0 + 4; q++) {
            uint32_t sw = (uint32_t)((q ^ (mrow & 7)) << 4);
            cp16(dst + base + sw, ga + q*8);
            cp16(dst + base + 16384u + sw, gb + q*8);
        }
    };
    load_st(0); CP_COMMIT();
    load_st(1); CP_COMMIT();
    for (int k = 0; k < NST; k++) {
        CP_WAIT1();
        __syncthreads();
        if (k + 2 < NST) load_st(k + 2);
        CP_COMMIT();
        uint32_t Ab = sb + (uint32_t)(k % 3)*32768u;
        mma_stage(Ab, Ab + 16384u, f, c);
    }
    __syncthreads();

    // ---------------- epilogue ----------------
    float* Cb = (float*)dsm;   // 128 x 132
    const int r0 = lane >> 2, c0 = lane & 3;
    #pragma unroll
    for (int t = 0; t < 2; t++) {
        int row = wm*32 + t*16 + r0;
        #pragma unroll
        for (int t2 = 0; t2 < 8; t2++) {
            int col = wn*64 + t2*8 + (c0 << 1);
            float b0s = sbias[col], b1s = sbias[col+1];
            float v0 = c[0==t? 0:1][t2][0]; // placeholder (rewritten below)
            v0 = c[t][t2][0] + b0s;
            float v1 = c[t][t2][1] + b1s;
            float v2 = c[t][t2][2] + b0s;
            float v3 = c[t][t2][3] + b1s;
            if (leaky) {
                v0 = (v0 >= 0.f) ? v0 : 0.01f*v0;
                v1 = (v1 >= 0.f) ? v1 : 0.01f*v1;
                v2 = (v2 >= 0.f) ? v2 : 0.01f*v2;
                v3 = (v3 >= 0.f) ? v3 : 0.01f*v3;
            }
            Cb[row*132 + col]       = v0;
            Cb[row*132 + col + 1]   = v1;
            Cb[(row+8)*132 + col]   = v2;
            Cb[(row+8)*132 + col+1] = v3;
        }
    }
    __syncthreads();

    if (res) {
        int co = tid >> 1, mh = (tid & 1) << 6;
        const float* rp = res + (size_t)b*256*SP + (size_t)co*SP + spb + mh;
        #pragma unroll
        for (int j4 = 0; j4 < 16; j4++) {
            float4 r4 = *(const float4*)(rp + j4*4);
            Cb[(mh + j4*4 + 0)*132 + co] += r4.x;
            Cb[(mh + j4*4 + 1)*132 + co] += r4.y;
            Cb[(mh + j4*4 + 2)*132 + co] += r4.z;
            Cb[(mh + j4*4 + 3)*132 + co] += r4.w;
        }
        __syncthreads();
    }

    if (outX) {
        int m = tid >> 1, ch = (tid & 1) << 6;
        int sp = spb + m; int d = sp / 3136; int r = sp - d*3136; int h = r / 56, w = r - h*56;
        size_t po = (size_t)(d+1)*PDH + (size_t)(h+1)*58 + (w+1);
        __half* xp = outX + ((size_t)b*PAD_SP + po)*128 + ch;
        #pragma unroll
        for (int j8 = 0; j8 < 8; j8++) {
            const float* p = &Cb[m*132 + ch + j8*8];
            __half2 h0 = __floats2half2_rn(p[0], p[1]);
            __half2 h1 = __floats2half2_rn(p[2], p[3]);
            __half2 h2 = __floats2half2_rn(p[4], p[5]);
            __half2 h3 = __floats2half2_rn(p[6], p[7]);
            uint4 u;
            u.x = *(uint32_t*)&h0; u.y = *(uint32_t*)&h1;
            u.z = *(uint32_t*)&h2; u.w = *(uint32_t*)&h3;
            *(uint4*)(xp + j8*8) = u;
        }
    }
    if (outN) {
        int co = tid >> 1, mh = (tid & 1) << 6;
        float* op = outN + (size_t)b*256*SP + (size_t)co*SP + spb + mh;
        #pragma unroll
        for (int j4 = 0; j4 < 16; j4++) {
            float4 o;
            o.x = Cb[(mh + j4*4 + 0)*132 + co];
            o.y = Cb[(mh + j4*4 + 1)*132 + co];
            o.z = Cb[(mh + j4*4 + 2)*132 + co];
            o.w = Cb[(mh + j4*4 + 3)*132 + co];
            *(float4*)(op + j4*4) = o;
        }
    }
}

// ---------------- launcher ----------------
extern "C" void kernel_launch(void* const* d_in, const int* in_sizes, int n_in,
                              void* d_out, int out_size)
{
    (void)in_sizes; (void)n_in; (void)out_size;
    const float* input  = (const float*)d_in[0];
    const float* n1w    = (const float*)d_in[1];
    const float* n1b    = (const float*)d_in[2];
    const float* n2w    = (const float*)d_in[3];
    const float* n2b    = (const float*)d_in[4];
    const float* wqkv   = (const float*)d_in[5];
    const float* wprojw = (const float*)d_in[6];
    const float* wprojb = (const float*)d_in[7];
    const float* wbias  = (const float*)d_in[8];
    const float* gqkv   = (const float*)d_in[9];
    const float* gprojw = (const float*)d_in[10];
    const float* gprojb = (const float*)d_in[11];
    const float* gbias  = (const float*)d_in[12];
    const float* f1c1w  = (const float*)d_in[13];
    const float* f1c1b  = (const float*)d_in[14];
    const float* f1c2w  = (const float*)d_in[15];
    const float* f1c2b  = (const float*)d_in[16];
    const float* g1c1w  = (const float*)d_in[17];
    const float* g1c1b  = (const float*)d_in[18];
    const float* g1c2w  = (const float*)d_in[19];
    const float* g1c2b  = (const float*)d_in[20];
    float* out = (float*)d_out;

    __half *xh, *qkvh, *atnh, *Xa, *Xb, *w2h, *wqkvh, *gqkvh, *wprjh, *gprjh;
    float *xw, *y, *s;
    cudaGetSymbolAddress((void**)&xh,    g_xh);
    cudaGetSymbolAddress((void**)&qkvh,  g_qkvh);
    cudaGetSymbolAddress((void**)&atnh,  g_atnh);
    cudaGetSymbolAddress((void**)&xw,    g_xw);
    cudaGetSymbolAddress((void**)&y,     g_y);
    cudaGetSymbolAddress((void**)&s,     g_s);
    cudaGetSymbolAddress((void**)&Xa,    g_Xa);
    cudaGetSymbolAddress((void**)&Xb,    g_Xb);
    cudaGetSymbolAddress((void**)&w2h,   g_w2h);
    cudaGetSymbolAddress((void**)&wqkvh, g_wqkvh);
    cudaGetSymbolAddress((void**)&gqkvh, g_gqkvh);
    cudaGetSymbolAddress((void**)&wprjh, g_wprjh);
    cudaGetSymbolAddress((void**)&gprjh, g_gprjh);

    const int ATTN_SMEM = (2*NTOK*64 + NTOK*NTOK) * (int)sizeof(float);
    cudaFuncSetAttribute(attn_kernel, cudaFuncAttributeMaxDynamicSharedMemorySize, ATTN_SMEM);
    const int TSMEM = 3 * 32768;   // 96KB: 3-stage ring; epilogue Cbuf aliases
    cudaFuncSetAttribute(hgemm_kernel<1>, cudaFuncAttributeMaxDynamicSharedMemorySize, TSMEM);
    cudaFuncSetAttribute(hgemm_kernel<0>, cudaFuncAttributeMaxDynamicSharedMemorySize, TSMEM);
    cudaFuncSetAttribute(conv_mma_kernel, cudaFuncAttributeMaxDynamicSharedMemorySize, TSMEM);

    // weight conversions
    f2h_kernel<<<768, 256>>>(wqkv, wqkvh, 768*256);
    f2h_kernel<<<768, 256>>>(gqkv, gqkvh, 768*256);
    f2h_kernel<<<256, 256>>>(wprojw, wprjh, 256*256);
    f2h_kernel<<<256, 256>>>(gprojw, gprjh, 256*256);

    // window attention block
    ln_in_kernel<<<1792, 256>>>(input, n1w, n1b, xh);
    hgemm_kernel<1><<<dim3(6, 392), 256, TSMEM>>>(xh, wqkvh, nullptr, nullptr, qkvh, 768);
    attn_kernel<<<dim3(512, 4), 128, ATTN_SMEM>>>(qkvh, wbias, atnh, 0);
    hgemm_kernel<0><<<dim3(2, 392), 256, TSMEM>>>(atnh, wprjh, wprojb, nullptr, xw, 256);
    // grid attention block
    ln_row_kernel<<<6272, 256>>>(xw, n2w, n2b, xh);
    hgemm_kernel<1><<<dim3(6, 392), 256, TSMEM>>>(xh, gqkvh, nullptr, nullptr, qkvh, 768);
    attn_kernel<<<dim3(512, 4), 128, ATTN_SMEM>>>(qkvh, gbias, atnh, 1);
    hgemm_kernel<0><<<dim3(2, 392), 256, TSMEM>>>(atnh, gprjh, gprojb, xw, y, 256);
    add_s_kernel<<<1568, 256>>>(input, y, s, Xa);

    // conv chain
    wt2_kernel<<<1728, 256>>>(f1c1w, w2h);
    conv_mma_kernel<<<392, 256, TSMEM>>>(Xa, w2h, f1c1b, nullptr, nullptr, Xb, 1);
    wt2_kernel<<<1728, 256>>>(f1c2w, w2h);
    conv_mma_kernel<<<392, 256, TSMEM>>>(Xb, w2h, f1c2b, s, out, Xa, 0);
    wt2_kernel<<<1728, 256>>>(g1c1w, w2h);
    conv_mma_kernel<<<392, 256, TSMEM>>>(Xa, w2h, g1c1b, nullptr, nullptr, Xb, 1);
    wt2_kernel<<<1728, 256>>>(g1c2w, w2h);
    conv_mma_kernel<<<392, 256, TSMEM>>>(Xb, w2h, g1c2b, s + (size_t)128*SP,
                                         out + (size_t)128*SP, nullptr, 0);
}

// round 6
// speedup vs baseline: 2.0037x; 1.0009x over previous
#include <cuda_runtime.h>
#include <cuda_fp16.h>
#include <cstdint>
#include <cstddef>

// ---------------- problem constants ----------------
#define SP    25088          // 8*56*56
#define T_TOK 50176          // 2*SP
#define NTOK  98
#define SCALE_Q 0.125f
#define PAD_SP 33640         // 10*58*58
#define PDH    3364          // 58*58

// ---------------- scratch ----------------
__device__ __half g_xh  [(size_t)T_TOK*256];
__device__ __half g_qkvh[(size_t)T_TOK*768];
__device__ __half g_atnh[(size_t)T_TOK*256];
__device__ float  g_xw  [(size_t)T_TOK*256];
__device__ float  g_y   [(size_t)T_TOK*256];
__device__ float  g_s   [(size_t)T_TOK*256];
__device__ __half g_Xa  [(size_t)2*PAD_SP*128];   // zero-init padding stays zero
__device__ __half g_Xb  [(size_t)2*PAD_SP*128];
__device__ __half g_w2h [27*128*128];             // [tap][co][ci]
__device__ __half g_wqkvh[768*256];
__device__ __half g_gqkvh[768*256];
__device__ __half g_wprjh[256*256];
__device__ __half g_gprjh[256*256];

// ---------------- PTX helpers (sm_80-baseline only) ----------------
__device__ __forceinline__ uint32_t smem_u32(const void* p) {
    uint32_t a;
    asm("{ .reg .u64 t; cvta.to.shared.u64 t, %1; cvt.u32.u64 %0, t; }" : "=r"(a) : "l"(p));
    return a;
}
__device__ __forceinline__ void cp16(uint32_t s, const void* g) {
    asm volatile("cp.async.cg.shared.global [%0], [%1], 16;" :: "r"(s), "l"(g));
}
#define CP_COMMIT() asm volatile("cp.async.commit_group;" ::: "memory")
#define CP_WAIT1()  asm volatile("cp.async.wait_group 1;"  ::: "memory")

__device__ __forceinline__ void ldsm4(uint32_t* r, uint32_t a) {
    asm volatile("ldmatrix.sync.aligned.m8n8.x4.shared.b16 {%0,%1,%2,%3}, [%4];"
        : "=r"(r[0]), "=r"(r[1]), "=r"(r[2]), "=r"(r[3]) : "r"(a));
}
#define MMA_F16(c, a, b0, b1) \
    asm volatile("mma.sync.aligned.m16n8k16.row.col.f32.f16.f16.f32 " \
        "{%0,%1,%2,%3}, {%4,%5,%6,%7}, {%8,%9}, {%0,%1,%2,%3};" \
        : "+f"((c)[0]), "+f"((c)[1]), "+f"((c)[2]), "+f"((c)[3]) \
        : "r"((a)[0]), "r"((a)[1]), "r"((a)[2]), "r"((a)[3]), "r"(b0), "r"(b1))

// ---------------- fp32 -> fp16 convert ----------------
__global__ void f2h_kernel(const float* __restrict__ src, __half* __restrict__ dst, int n)
{
    int i = blockIdx.x*256 + threadIdx.x;
    if (i < n) dst[i] = __float2half_rn(src[i]);
}

// ---------------- LN kernels (output half) ----------------
__global__ __launch_bounds__(256) void ln_in_kernel(
    const float* __restrict__ in, const float* __restrict__ w,
    const float* __restrict__ b, __half* __restrict__ out)
{
    __shared__ float s[28][257];
    int bx = blockIdx.x;
    int wt = bx & 1; int tmp = bx >> 1;
    int h = tmp % 56; tmp /= 56;
    int d = tmp & 7; int bb = tmp >> 3;
    int w0 = wt * 28;
    size_t sp = ((size_t)d*56 + h)*56 + w0;
    const float* ib = in + (size_t)bb*256*SP + sp;
    for (int i = threadIdx.x; i < 28*256; i += 256) {
        int c = i / 28, ww_ = i - c*28;
        s[ww_][c] = ib[(size_t)c*SP + ww_];
    }
    __syncthreads();
    int warp = threadIdx.x >> 5, lane = threadIdx.x & 31;
    for (int tk = warp; tk < 28; tk += 8) {
        float s1 = 0.f, s2 = 0.f;
        #pragma unroll
        for (int j = 0; j < 8; j++) { float v = s[tk][lane + (j<<5)]; s1 += v; s2 += v*v; }
        #pragma unroll
        for (int o = 16; o; o >>= 1) {
            s1 += __shfl_xor_sync(0xffffffffu, s1, o);
            s2 += __shfl_xor_sync(0xffffffffu, s2, o);
        }
        float m = s1 * (1.f/256.f);
        float var = s2 * (1.f/256.f) - m*m;
        float iv = rsqrtf(var + 1e-5f);
        size_t t = (size_t)bb*SP + sp + tk;
        __half* orow = out + t*256;
        #pragma unroll
        for (int j = 0; j < 8; j++) {
            int c = lane + (j<<5);
            orow[c] = __float2half_rn((s[tk][c] - m) * iv * w[c] + b[c]);
        }
    }
}

__global__ __launch_bounds__(256) void ln_row_kernel(
    const float* __restrict__ in, const float* __restrict__ w,
    const float* __restrict__ b, __half* __restrict__ out)
{
    int t = blockIdx.x*8 + (threadIdx.x >> 5);
    int lane = threadIdx.x & 31;
    const float* row = in + (size_t)t*256;
    float v[8]; float s1 = 0.f, s2 = 0.f;
    #pragma unroll
    for (int j = 0; j < 8; j++) { v[j] = row[lane + (j<<5)]; s1 += v[j]; s2 += v[j]*v[j]; }
    #pragma unroll
    for (int o = 16; o; o >>= 1) {
        s1 += __shfl_xor_sync(0xffffffffu, s1, o);
        s2 += __shfl_xor_sync(0xffffffffu, s2, o);
    }
    float m = s1 * (1.f/256.f);
    float var = s2 * (1.f/256.f) - m*m;
    float iv = rsqrtf(var + 1e-5f);
    __half* orow = out + (size_t)t*256;
    #pragma unroll
    for (int j = 0; j < 8; j++) {
        int c = lane + (j<<5);
        orow[c] = __float2half_rn((v[j] - m) * iv * w[c] + b[c]);
    }
}

// ---------------- shared warp-MMA stage: 128x128 tile, BK=64 ----------------
// smem tile layout: 128 rows x 64 halves (128B, 8 chunks of 16B), chunk swizzle c^(row&7)
// 8 warps = 4(M) x 2(N); warp tile 32x64.
struct FragCtx {
    uint32_t aoff;    // A row byte offset (lane)
    uint32_t boff;    // B row byte offset (lane, group 0)
    uint32_t axor[4]; // per kk: A chunk xor term <<4
    uint32_t bxor[4]; // per kk: B chunk xor term <<4
};
__device__ __forceinline__ FragCtx make_frag_ctx(int lane, int wm, int wn) {
    FragCtx f;
    int l7 = lane & 7;
    f.aoff = (uint32_t)((wm*32 + ((lane>>3)&1)*8 + l7) * 128);
    f.boff = (uint32_t)((wn*64 + ((lane>>4)&1)*8 + l7) * 128);
    #pragma unroll
    for (int kk = 0; kk < 4; kk++) {
        f.axor[kk] = (uint32_t)(((2*kk + (lane>>4)) ^ l7) << 4);
        f.bxor[kk] = (uint32_t)(((2*kk + ((lane>>3)&1)) ^ l7) << 4);
    }
    return f;
}
__device__ __forceinline__ void mma_stage(uint32_t Ab, uint32_t Bb,
                                          const FragCtx& f, float c[2][8][4])
{
    #pragma unroll
    for (int kk = 0; kk < 4; kk++) {
        uint32_t a0[4], a1[4];
        ldsm4(a0, Ab + f.aoff + f.axor[kk]);
        ldsm4(a1, Ab + f.aoff + 2048u + f.axor[kk]);
        #pragma unroll
        for (int g = 0; g < 4; g++) {
            uint32_t bb[4];
            ldsm4(bb, Bb + f.boff + (uint32_t)g*2048u + f.bxor[kk]);
            MMA_F16(c[0][2*g],   a0, bb[0], bb[1]);
            MMA_F16(c[1][2*g],   a1, bb[0], bb[1]);
            MMA_F16(c[0][2*g+1], a0, bb[2], bb[3]);
            MMA_F16(c[1][2*g+1], a1, bb[2], bb[3]);
        }
    }
}

// ---------------- fp16 GEMM: C[M,N] = A[M,256] @ B[N,256]^T (+bias)(+res) --------------
// grid (N/128, 392); OUTHALF: 1 -> C half, 0 -> C float
template<int OUTHALF>
__global__ __launch_bounds__(256, 2) void hgemm_kernel(
    const __half* __restrict__ A, const __half* __restrict__ B,
    const float* __restrict__ bias, const float* __restrict__ res,
    void* __restrict__ Cout, int N)
{
    extern __shared__ __align__(16) char dsm[];
    __shared__ float sbias[128];
    const int tid = threadIdx.x, lane = tid & 31, wid = tid >> 5;
    const int wm = wid & 3, wn = wid >> 2;
    const int bx = blockIdx.x, by = blockIdx.y;

    sbias[tid >> 1] = 0.f;  // covered twice; then real load
    if (bias && tid < 128) sbias[tid] = bias[bx*128 + tid];
    else if (tid < 128 && !bias) sbias[tid] = 0.f;

    const int mrow = tid >> 1;
    const int q0 = (tid & 1) * 4;
    const __half* asrc = A + ((size_t)(by*128 + mrow))*256;
    const __half* bsrc = B + ((size_t)(bx*128 + mrow))*256;
    const uint32_t sb = smem_u32(dsm);
    const uint32_t dst = sb + (uint32_t)mrow*128u;
    FragCtx f = make_frag_ctx(lane, wm, wn);

    float c[2][8][4];
    #pragma unroll
    for (int t = 0; t < 2; t++)
        #pragma unroll
        for (int j = 0; j < 8; j++)
            #pragma unroll
            for (int q = 0; q < 4; q++) c[t][j][q] = 0.f;

    auto load_st = [&](int s) {
        uint32_t base = (uint32_t)(s % 3) * 32768u;
        #pragma unroll
        for (int q = q0; q < q0 + 4; q++) {
            uint32_t sw = (uint32_t)((q ^ (mrow & 7)) << 4);
            cp16(dst + base + sw, asrc + s*64 + q*8);
            cp16(dst + base + 16384u + sw, bsrc + s*64 + q*8);
        }
    };
    load_st(0); CP_COMMIT();
    load_st(1); CP_COMMIT();
    #pragma unroll
    for (int k = 0; k < 4; k++) {
        CP_WAIT1();
        __syncthreads();
        if (k + 2 < 4) load_st(k + 2);
        CP_COMMIT();
        uint32_t Ab = sb + (uint32_t)(k % 3)*32768u;
        mma_stage(Ab, Ab + 16384u, f, c);
    }
    __syncthreads();

    // epilogue via Cbuf
    float* Cb = (float*)dsm;   // 128 x 132
    const int r0 = lane >> 2, c0 = lane & 3;
    #pragma unroll
    for (int t = 0; t < 2; t++) {
        int row = wm*32 + t*16 + r0;
        #pragma unroll
        for (int t2 = 0; t2 < 8; t2++) {
            int col = wn*64 + t2*8 + (c0 << 1);
            Cb[row*132 + col]       = c[t][t2][0] + sbias[col];
            Cb[row*132 + col + 1]   = c[t][t2][1] + sbias[col+1];
            Cb[(row+8)*132 + col]   = c[t][t2][2] + sbias[col];
            Cb[(row+8)*132 + col+1] = c[t][t2][3] + sbias[col+1];
        }
    }
    __syncthreads();

    const int m = tid >> 1, ch = (tid & 1) << 6;
    size_t goff = ((size_t)(by*128 + m))*N + bx*128 + ch;
    if (OUTHALF) {
        __half* Ch = (__half*)Cout;
        #pragma unroll
        for (int j8 = 0; j8 < 8; j8++) {
            uint4 u;
            const float* p = &Cb[m*132 + ch + j8*8];
            u.x = __half2half2(__float2half_rn(0.f)).x; // placeholder overwritten below
            __half2 h0 = __floats2half2_rn(p[0], p[1]);
            __half2 h1 = __floats2half2_rn(p[2], p[3]);
            __half2 h2 = __floats2half2_rn(p[4], p[5]);
            __half2 h3 = __floats2half2_rn(p[6], p[7]);
            u.x = *(uint32_t*)&h0; u.y = *(uint32_t*)&h1;
            u.z = *(uint32_t*)&h2; u.w = *(uint32_t*)&h3;
            *(uint4*)(Ch + goff + j8*8) = u;
        }
    } else {
        float* Cf = (float*)Cout;
        #pragma unroll
        for (int j4 = 0; j4 < 16; j4++) {
            float4 v = *(const float4*)&Cb[m*132 + ch + j4*4];
            if (res) {
                float4 r = *(const float4*)(res + goff + j4*4);
                v.x += r.x; v.y += r.y; v.z += r.z; v.w += r.w;
            }
            *(float4*)(Cf + goff + j4*4) = v;
        }
    }
}

// ---------------- attention (half in/out, fp32 math) ----------------
__global__ __launch_bounds__(128) void attn_kernel(
    const __half* __restrict__ qkv, const float* __restrict__ btab,
    __half* __restrict__ out, int grid_mode)
{
    extern __shared__ float sm[];
    float* ks = sm;
    float* vs = sm + NTOK*64;
    float* sc = sm + 2*NTOK*64;
    __shared__ int ts[NTOK];
    int wi = blockIdx.x, head = blockIdx.y;
    int b = wi >> 8, wd = (wi>>6)&3, wh = (wi>>3)&7, ww = wi & 7;
    int tid = threadIdx.x;
    if (tid < NTOK) {
        int pd = tid / 49; int r7 = tid - pd*49; int ph = r7 / 7, pw = r7 - ph*7;
        int d, h, w;
        if (grid_mode) { d = pd*4 + wd; h = ph*8 + wh; w = pw*8 + ww; }
        else           { d = wd*2 + pd; h = wh*7 + ph; w = ww*7 + pw; }
        ts[tid] = ((b*8 + d)*56 + h)*56 + w;
    }
    __syncthreads();
    int hoff = head << 6;
    for (int i = tid; i < NTOK*64; i += 128) {
        int r = i >> 6, c = i & 63;
        size_t base = (size_t)ts[r]*768 + hoff + c;
        ks[i] = __half2float(qkv[base + 256]);
        vs[i] = __half2float(qkv[base + 512]);
    }
    __syncthreads();
    int r = tid;
    if (r < NTOK) {
        float4 q4[16];
        const __half2* qp = (const __half2*)(qkv + (size_t)ts[r]*768 + hoff);
        #pragma unroll
        for (int i = 0; i < 16; i++) {
            float2 f0 = __half22float2(qp[2*i]);
            float2 f1 = __half22float2(qp[2*i+1]);
            q4[i] = make_float4(f0.x*SCALE_Q, f0.y*SCALE_Q, f1.x*SCALE_Q, f1.y*SCALE_Q);
        }
        int pd_r = r / 49; int rr = r - pd_r*49; int ph_r = rr/7, pw_r = rr - ph_r*7;
        float mx = -1e30f;
        for (int m = 0; m < NTOK; m++) {
            const float4* kk = (const float4*)(ks + (m<<6));
            float s0=0.f,s1=0.f,s2=0.f,s3=0.f;
            #pragma unroll
            for (int i = 0; i < 16; i += 4) {
                float4 k0 = kk[i+0];
                s0 += q4[i+0].x*k0.x + q4[i+0].y*k0.y + q4[i+0].z*k0.z + q4[i+0].w*k0.w;
                float4 k1 = kk[i+1];
                s1 += q4[i+1].x*k1.x + q4[i+1].y*k1.y + q4[i+1].z*k1.z + q4[i+1].w*k1.w;
                float4 k2 = kk[i+2];
                s2 += q4[i+2].x*k2.x + q4[i+2].y*k2.y + q4[i+2].z*k2.z + q4[i+2].w*k2.w;
                float4 k3 = kk[i+3];
                s3 += q4[i+3].x*k3.x + q4[i+3].y*k3.y + q4[i+3].z*k3.z + q4[i+3].w*k3.w;
            }
            int pd_m = m / 49; int mm = m - pd_m*49; int ph_m = mm/7, pw_m = mm - ph_m*7;
            int rpi = ((pd_r - pd_m + 1)*13 + (ph_r - ph_m + 6))*13 + (pw_r - pw_m + 6);
            float s = (s0+s1) + (s2+s3) + btab[(rpi<<2) + head];
            sc[r*NTOK + m] = s;
            mx = fmaxf(mx, s);
        }
        float sum = 0.f;
        for (int m = 0; m < NTOK; m++) {
            float e = __expf(sc[r*NTOK + m] - mx);
            sc[r*NTOK + m] = e; sum += e;
        }
        float inv = 1.f / sum;
        float4 a4[16];
        #pragma unroll
        for (int i = 0; i < 16; i++) a4[i] = make_float4(0.f,0.f,0.f,0.f);
        for (int m = 0; m < NTOK; m++) {
            float a = sc[r*NTOK + m] * inv;
            const float4* vv = (const float4*)(vs + (m<<6));
            #pragma unroll
            for (int i = 0; i < 16; i++) {
                float4 v = vv[i];
                a4[i].x += a*v.x; a4[i].y += a*v.y; a4[i].z += a*v.z; a4[i].w += a*v.w;
            }
        }
        __half2* op = (__half2*)(out + (size_t)ts[r]*256 + hoff);
        #pragma unroll
        for (int i = 0; i < 16; i++) {
            op[2*i]   = __floats2half2_rn(a4[i].x, a4[i].y);
            op[2*i+1] = __floats2half2_rn(a4[i].z, a4[i].w);
        }
    }
}

// ---------------- s = input + y (fp32 NCDHW) + padded half s2 -> Xa ----------------
__global__ __launch_bounds__(256) void add_s_kernel(
    const float* __restrict__ in, const float* __restrict__ y,
    float* __restrict__ s, __half* __restrict__ Xa)
{
    __shared__ float sm[256][33];
    int b0 = blockIdx.x * 32;
    for (int i = threadIdx.x; i < 32*256; i += 256) {
        int tk = i >> 8, c = i & 255;
        sm[c][tk] = y[(size_t)(b0 + tk)*256 + c];
    }
    __syncthreads();
    int b = b0 / SP; int sp0 = b0 % SP;
    for (int i = threadIdx.x; i < 32*256; i += 256) {
        int c = i >> 5, k = i & 31;
        size_t gi = ((size_t)b*256 + c)*SP + sp0 + k;
        float v = in[gi] + sm[c][k];
        s[gi] = v;
        sm[c][k] = v;
    }
    __syncthreads();
    for (int i = threadIdx.x; i < 32*128; i += 256) {
        int tok = i >> 7, ci = i & 127;
        int sp = sp0 + tok;
        int d = sp / 3136; int r = sp - d*3136; int h = r / 56, w = r - h*56;
        int pad = (d+1)*PDH + (h+1)*58 + (w+1);
        Xa[((size_t)b*PAD_SP + pad)*128 + ci] = __float2half_rn(sm[128+ci][tok]);
    }
}

// ---------------- conv weight transform: [co][ci][tap] -> [tap][co][ci] half ----------
__global__ void wt2_kernel(const float* __restrict__ w, __half* __restrict__ o)
{
    int i = blockIdx.x*256 + threadIdx.x;
    if (i >= 27*128*128) return;
    int ci = i & 127; int r = i >> 7; int co = r & 127; int tap = r >> 7;
    o[i] = __float2half_rn(w[(co*128 + ci)*27 + tap]);
}

// ---------------- fp16 implicit-GEMM conv ----------------
// M=128 positions x N=128 co; K = 27 taps x 128 ci as 54 stages of 64.
__global__ __launch_bounds__(256, 2) void conv_mma_kernel(
    const __half* __restrict__ Xin, const __half* __restrict__ w2,
    const float* __restrict__ bias, const float* __restrict__ res,
    float* __restrict__ outN, __half* __restrict__ outX, int leaky)
{
    extern __shared__ __align__(16) char dsm[];
    __shared__ float sbias[128];

    const int tid = threadIdx.x, lane = tid & 31, wid = tid >> 5;
    const int wm = wid & 3, wn = wid >> 2;
    const int bx = blockIdx.x;
    const int b = bx / 196;
    const int spb = (bx % 196) * 128;

    if (tid < 128) sbias[tid] = bias[tid];

    const int mrow = tid >> 1;
    const int q0 = (tid & 1) * 4;
    int sp_c = spb + mrow;
    int d_c = sp_c / 3136; int r_c = sp_c - d_c*3136; int h_c = r_c / 56, w_c = r_c - h_c*56;
    const int padrow = d_c*PDH + h_c*58 + w_c;
    const __half* XinB = Xin + (size_t)b * PAD_SP * 128;
    const uint32_t sb = smem_u32(dsm);
    const uint32_t dst = sb + (uint32_t)mrow*128u;
    FragCtx f = make_frag_ctx(lane, wm, wn);

    float c[2][8][4];
    #pragma unroll
    for (int t = 0; t < 2; t++)
        #pragma unroll
        for (int j = 0; j < 8; j++)
            #pragma unroll
            for (int q = 0; q < 4; q++) c[t][j][q] = 0.f;

    const int NST = 54;
    auto load_st = [&](int s) {
        int tap = s >> 1, kh64 = (s & 1) * 64;
        int kd = tap / 9; int rem = tap - kd*9; int kh = rem / 3, kw = rem - kh*3;
        int toff = kd*PDH + kh*58 + kw;
        uint32_t base = (uint32_t)(s % 3) * 32768u;
        const __half* ga = XinB + (size_t)(padrow + toff)*128 + kh64;
        const __half* gb = w2 + ((size_t)tap*128 + mrow)*128 + kh64;
        #pragma unroll
        for (int q = q0; q < q0 + 4; q++) {
            uint32_t sw = (uint32_t)((q ^ (mrow & 7)) << 4);
            cp16(dst + base + sw, ga + q*8);
            cp16(dst + base + 16384u + sw, gb + q*8);
        }
    };
    load_st(0); CP_COMMIT();
    load_st(1); CP_COMMIT();
    for (int k = 0; k < NST; k++) {
        CP_WAIT1();
        __syncthreads();
        if (k + 2 < NST) load_st(k + 2);
        CP_COMMIT();
        uint32_t Ab = sb + (uint32_t)(k % 3)*32768u;
        mma_stage(Ab, Ab + 16384u, f, c);
    }
    __syncthreads();

    // ---------------- epilogue ----------------
    float* Cb = (float*)dsm;   // 128 x 132
    const int r0 = lane >> 2, c0 = lane & 3;
    #pragma unroll
    for (int t = 0; t < 2; t++) {
        int row = wm*32 + t*16 + r0;
        #pragma unroll
        for (int t2 = 0; t2 < 8; t2++) {
            int col = wn*64 + t2*8 + (c0 << 1);
            float b0s = sbias[col], b1s = sbias[col+1];
            float v0 = c[0==t? 0:1][t2][0]; // placeholder (rewritten below)
            v0 = c[t][t2][0] + b0s;
            float v1 = c[t][t2][1] + b1s;
            float v2 = c[t][t2][2] + b0s;
            float v3 = c[t][t2][3] + b1s;
            if (leaky) {
                v0 = (v0 >= 0.f) ? v0 : 0.01f*v0;
                v1 = (v1 >= 0.f) ? v1 : 0.01f*v1;
                v2 = (v2 >= 0.f) ? v2 : 0.01f*v2;
                v3 = (v3 >= 0.f) ? v3 : 0.01f*v3;
            }
            Cb[row*132 + col]       = v0;
            Cb[row*132 + col + 1]   = v1;
            Cb[(row+8)*132 + col]   = v2;
            Cb[(row+8)*132 + col+1] = v3;
        }
    }
    __syncthreads();

    if (res) {
        int co = tid >> 1, mh = (tid & 1) << 6;
        const float* rp = res + (size_t)b*256*SP + (size_t)co*SP + spb + mh;
        #pragma unroll
        for (int j4 = 0; j4 < 16; j4++) {
            float4 r4 = *(const float4*)(rp + j4*4);
            Cb[(mh + j4*4 + 0)*132 + co] += r4.x;
            Cb[(mh + j4*4 + 1)*132 + co] += r4.y;
            Cb[(mh + j4*4 + 2)*132 + co] += r4.z;
            Cb[(mh + j4*4 + 3)*132 + co] += r4.w;
        }
        __syncthreads();
    }

    if (outX) {
        int m = tid >> 1, ch = (tid & 1) << 6;
        int sp = spb + m; int d = sp / 3136; int r = sp - d*3136; int h = r / 56, w = r - h*56;
        size_t po = (size_t)(d+1)*PDH + (size_t)(h+1)*58 + (w+1);
        __half* xp = outX + ((size_t)b*PAD_SP + po)*128 + ch;
        #pragma unroll
        for (int j8 = 0; j8 < 8; j8++) {
            const float* p = &Cb[m*132 + ch + j8*8];
            __half2 h0 = __floats2half2_rn(p[0], p[1]);
            __half2 h1 = __floats2half2_rn(p[2], p[3]);
            __half2 h2 = __floats2half2_rn(p[4], p[5]);
            __half2 h3 = __floats2half2_rn(p[6], p[7]);
            uint4 u;
            u.x = *(uint32_t*)&h0; u.y = *(uint32_t*)&h1;
            u.z = *(uint32_t*)&h2; u.w = *(uint32_t*)&h3;
            *(uint4*)(xp + j8*8) = u;
        }
    }
    if (outN) {
        int co = tid >> 1, mh = (tid & 1) << 6;
        float* op = outN + (size_t)b*256*SP + (size_t)co*SP + spb + mh;
        #pragma unroll
        for (int j4 = 0; j4 < 16; j4++) {
            float4 o;
            o.x = Cb[(mh + j4*4 + 0)*132 + co];
            o.y = Cb[(mh + j4*4 + 1)*132 + co];
            o.z = Cb[(mh + j4*4 + 2)*132 + co];
            o.w = Cb[(mh + j4*4 + 3)*132 + co];
            *(float4*)(op + j4*4) = o;
        }
    }
}

// ---------------- launcher ----------------
extern "C" void kernel_launch(void* const* d_in, const int* in_sizes, int n_in,
                              void* d_out, int out_size)
{
    (void)in_sizes; (void)n_in; (void)out_size;
    const float* input  = (const float*)d_in[0];
    const float* n1w    = (const float*)d_in[1];
    const float* n1b    = (const float*)d_in[2];
    const float* n2w    = (const float*)d_in[3];
    const float* n2b    = (const float*)d_in[4];
    const float* wqkv   = (const float*)d_in[5];
    const float* wprojw = (const float*)d_in[6];
    const float* wprojb = (const float*)d_in[7];
    const float* wbias  = (const float*)d_in[8];
    const float* gqkv   = (const float*)d_in[9];
    const float* gprojw = (const float*)d_in[10];
    const float* gprojb = (const float*)d_in[11];
    const float* gbias  = (const float*)d_in[12];
    const float* f1c1w  = (const float*)d_in[13];
    const float* f1c1b  = (const float*)d_in[14];
    const float* f1c2w  = (const float*)d_in[15];
    const float* f1c2b  = (const float*)d_in[16];
    const float* g1c1w  = (const float*)d_in[17];
    const float* g1c1b  = (const float*)d_in[18];
    const float* g1c2w  = (const float*)d_in[19];
    const float* g1c2b  = (const float*)d_in[20];
    float* out = (float*)d_out;

    __half *xh, *qkvh, *atnh, *Xa, *Xb, *w2h, *wqkvh, *gqkvh, *wprjh, *gprjh;
    float *xw, *y, *s;
    cudaGetSymbolAddress((void**)&xh,    g_xh);
    cudaGetSymbolAddress((void**)&qkvh,  g_qkvh);
    cudaGetSymbolAddress((void**)&atnh,  g_atnh);
    cudaGetSymbolAddress((void**)&xw,    g_xw);
    cudaGetSymbolAddress((void**)&y,     g_y);
    cudaGetSymbolAddress((void**)&s,     g_s);
    cudaGetSymbolAddress((void**)&Xa,    g_Xa);
    cudaGetSymbolAddress((void**)&Xb,    g_Xb);
    cudaGetSymbolAddress((void**)&w2h,   g_w2h);
    cudaGetSymbolAddress((void**)&wqkvh, g_wqkvh);
    cudaGetSymbolAddress((void**)&gqkvh, g_gqkvh);
    cudaGetSymbolAddress((void**)&wprjh, g_wprjh);
    cudaGetSymbolAddress((void**)&gprjh, g_gprjh);

    const int ATTN_SMEM = (2*NTOK*64 + NTOK*NTOK) * (int)sizeof(float);
    cudaFuncSetAttribute(attn_kernel, cudaFuncAttributeMaxDynamicSharedMemorySize, ATTN_SMEM);
    const int TSMEM = 3 * 32768;   // 96KB: 3-stage ring; epilogue Cbuf aliases
    cudaFuncSetAttribute(hgemm_kernel<1>, cudaFuncAttributeMaxDynamicSharedMemorySize, TSMEM);
    cudaFuncSetAttribute(hgemm_kernel<0>, cudaFuncAttributeMaxDynamicSharedMemorySize, TSMEM);
    cudaFuncSetAttribute(conv_mma_kernel, cudaFuncAttributeMaxDynamicSharedMemorySize, TSMEM);

    // weight conversions
    f2h_kernel<<<768, 256>>>(wqkv, wqkvh, 768*256);
    f2h_kernel<<<768, 256>>>(gqkv, gqkvh, 768*256);
    f2h_kernel<<<256, 256>>>(wprojw, wprjh, 256*256);
    f2h_kernel<<<256, 256>>>(gprojw, gprjh, 256*256);

    // window attention block
    ln_in_kernel<<<1792, 256>>>(input, n1w, n1b, xh);
    hgemm_kernel<1><<<dim3(6, 392), 256, TSMEM>>>(xh, wqkvh, nullptr, nullptr, qkvh, 768);
    attn_kernel<<<dim3(512, 4), 128, ATTN_SMEM>>>(qkvh, wbias, atnh, 0);
    hgemm_kernel<0><<<dim3(2, 392), 256, TSMEM>>>(atnh, wprjh, wprojb, nullptr, xw, 256);
    // grid attention block
    ln_row_kernel<<<6272, 256>>>(xw, n2w, n2b, xh);
    hgemm_kernel<1><<<dim3(6, 392), 256, TSMEM>>>(xh, gqkvh, nullptr, nullptr, qkvh, 768);
    attn_kernel<<<dim3(512, 4), 128, ATTN_SMEM>>>(qkvh, gbias, atnh, 1);
    hgemm_kernel<0><<<dim3(2, 392), 256, TSMEM>>>(atnh, gprjh, gprojb, xw, y, 256);
    add_s_kernel<<<1568, 256>>>(input, y, s, Xa);

    // conv chain
    wt2_kernel<<<1728, 256>>>(f1c1w, w2h);
    conv_mma_kernel<<<392, 256, TSMEM>>>(Xa, w2h, f1c1b, nullptr, nullptr, Xb, 1);
    wt2_kernel<<<1728, 256>>>(f1c2w, w2h);
    conv_mma_kernel<<<392, 256, TSMEM>>>(Xb, w2h, f1c2b, s, out, Xa, 0);
    wt2_kernel<<<1728, 256>>>(g1c1w, w2h);
    conv_mma_kernel<<<392, 256, TSMEM>>>(Xa, w2h, g1c1b, nullptr, nullptr, Xb, 1);
    wt2_kernel<<<1728, 256>>>(g1c2w, w2h);
    conv_mma_kernel<<<392, 256, TSMEM>>>(Xb, w2h, g1c2b, s + (size_t)128*SP,
                                         out + (size_t)128*SP, nullptr, 0);
}

// round 7
// speedup vs baseline: 3.2011x; 1.5976x over previous
#include <cuda_runtime.h>
#include <cuda_fp16.h>
#include <cstdint>
#include <cstddef>

// ---------------- problem constants ----------------
#define SP    25088          // 8*56*56
#define T_TOK 50176          // 2*SP
#define NTOK  98
#define SCALE_Q 0.125f
#define PAD_SP 33640         // 10*58*58
#define PDH    3364          // 58*58

// ---------------- scratch ----------------
__device__ __half g_xh  [(size_t)T_TOK*256];
__device__ __half g_qkvh[(size_t)T_TOK*768];
__device__ __half g_atnh[(size_t)T_TOK*256];
__device__ float  g_xw  [(size_t)T_TOK*256];
__device__ float  g_y   [(size_t)T_TOK*256];
__device__ float  g_s   [(size_t)T_TOK*256];
__device__ __half g_Xa  [(size_t)2*PAD_SP*128];   // zero-init padding stays zero
__device__ __half g_Xb  [(size_t)2*PAD_SP*128];
__device__ __half g_w2h [27*128*128];             // [tap][co][ci]
__device__ __half g_wqkvh[768*256];
__device__ __half g_gqkvh[768*256];
__device__ __half g_wprjh[256*256];
__device__ __half g_gprjh[256*256];
__device__ float  g_bmat[4*128*112];              // bias matrix [head][r][m]

// ---------------- PTX helpers (sm_80-baseline only) ----------------
__device__ __forceinline__ uint32_t smem_u32(const void* p) {
    uint32_t a;
    asm("{ .reg .u64 t; cvta.to.shared.u64 t, %1; cvt.u32.u64 %0, t; }" : "=r"(a) : "l"(p));
    return a;
}
__device__ __forceinline__ void cp16(uint32_t s, const void* g) {
    asm volatile("cp.async.cg.shared.global [%0], [%1], 16;" :: "r"(s), "l"(g));
}
#define CP_COMMIT() asm volatile("cp.async.commit_group;" ::: "memory")
#define CP_WAIT1()  asm volatile("cp.async.wait_group 1;"  ::: "memory")

__device__ __forceinline__ void ldsm4(uint32_t* r, uint32_t a) {
    asm volatile("ldmatrix.sync.aligned.m8n8.x4.shared.b16 {%0,%1,%2,%3}, [%4];"
        : "=r"(r[0]), "=r"(r[1]), "=r"(r[2]), "=r"(r[3]) : "r"(a));
}
__device__ __forceinline__ void ldsm4t(uint32_t* r, uint32_t a) {
    asm volatile("ldmatrix.sync.aligned.m8n8.x4.trans.shared.b16 {%0,%1,%2,%3}, [%4];"
        : "=r"(r[0]), "=r"(r[1]), "=r"(r[2]), "=r"(r[3]) : "r"(a));
}
#define MMA_F16(c, a, b0, b1) \
    asm volatile("mma.sync.aligned.m16n8k16.row.col.f32.f16.f16.f32 " \
        "{%0,%1,%2,%3}, {%4,%5,%6,%7}, {%8,%9}, {%0,%1,%2,%3};" \
        : "+f"((c)[0]), "+f"((c)[1]), "+f"((c)[2]), "+f"((c)[3]) \
        : "r"((a)[0]), "r"((a)[1]), "r"((a)[2]), "r"((a)[3]), "r"(b0), "r"(b1))

// ---------------- fp32 -> fp16 convert ----------------
__global__ void f2h_kernel(const float* __restrict__ src, __half* __restrict__ dst, int n)
{
    int i = blockIdx.x*256 + threadIdx.x;
    if (i < n) dst[i] = __float2half_rn(src[i]);
}

// ---------------- LN kernels (output half) ----------------
__global__ __launch_bounds__(256) void ln_in_kernel(
    const float* __restrict__ in, const float* __restrict__ w,
    const float* __restrict__ b, __half* __restrict__ out)
{
    __shared__ float s[28][257];
    int bx = blockIdx.x;
    int wt = bx & 1; int tmp = bx >> 1;
    int h = tmp % 56; tmp /= 56;
    int d = tmp & 7; int bb = tmp >> 3;
    int w0 = wt * 28;
    size_t sp = ((size_t)d*56 + h)*56 + w0;
    const float* ib = in + (size_t)bb*256*SP + sp;
    for (int i = threadIdx.x; i < 28*256; i += 256) {
        int c = i / 28, ww_ = i - c*28;
        s[ww_][c] = ib[(size_t)c*SP + ww_];
    }
    __syncthreads();
    int warp = threadIdx.x >> 5, lane = threadIdx.x & 31;
    for (int tk = warp; tk < 28; tk += 8) {
        float s1 = 0.f, s2 = 0.f;
        #pragma unroll
        for (int j = 0; j < 8; j++) { float v = s[tk][lane + (j<<5)]; s1 += v; s2 += v*v; }
        #pragma unroll
        for (int o = 16; o; o >>= 1) {
            s1 += __shfl_xor_sync(0xffffffffu, s1, o);
            s2 += __shfl_xor_sync(0xffffffffu, s2, o);
        }
        float m = s1 * (1.f/256.f);
        float var = s2 * (1.f/256.f) - m*m;
        float iv = rsqrtf(var + 1e-5f);
        size_t t = (size_t)bb*SP + sp + tk;
        __half* orow = out + t*256;
        #pragma unroll
        for (int j = 0; j < 8; j++) {
            int c = lane + (j<<5);
            orow[c] = __float2half_rn((s[tk][c] - m) * iv * w[c] + b[c]);
        }
    }
}

__global__ __launch_bounds__(256) void ln_row_kernel(
    const float* __restrict__ in, const float* __restrict__ w,
    const float* __restrict__ b, __half* __restrict__ out)
{
    int t = blockIdx.x*8 + (threadIdx.x >> 5);
    int lane = threadIdx.x & 31;
    const float* row = in + (size_t)t*256;
    float v[8]; float s1 = 0.f, s2 = 0.f;
    #pragma unroll
    for (int j = 0; j < 8; j++) { v[j] = row[lane + (j<<5)]; s1 += v[j]; s2 += v[j]*v[j]; }
    #pragma unroll
    for (int o = 16; o; o >>= 1) {
        s1 += __shfl_xor_sync(0xffffffffu, s1, o);
        s2 += __shfl_xor_sync(0xffffffffu, s2, o);
    }
    float m = s1 * (1.f/256.f);
    float var = s2 * (1.f/256.f) - m*m;
    float iv = rsqrtf(var + 1e-5f);
    __half* orow = out + (size_t)t*256;
    #pragma unroll
    for (int j = 0; j < 8; j++) {
        int c = lane + (j<<5);
        orow[c] = __float2half_rn((v[j] - m) * iv * w[c] + b[c]);
    }
}

// ---------------- shared warp-MMA stage: 128x128 tile, BK=64 ----------------
struct FragCtx {
    uint32_t aoff;
    uint32_t boff;
    uint32_t axor[4];
    uint32_t bxor[4];
};
__device__ __forceinline__ FragCtx make_frag_ctx(int lane, int wm, int wn) {
    FragCtx f;
    int l7 = lane & 7;
    f.aoff = (uint32_t)((wm*32 + ((lane>>3)&1)*8 + l7) * 128);
    f.boff = (uint32_t)((wn*64 + ((lane>>4)&1)*8 + l7) * 128);
    #pragma unroll
    for (int kk = 0; kk < 4; kk++) {
        f.axor[kk] = (uint32_t)(((2*kk + (lane>>4)) ^ l7) << 4);
        f.bxor[kk] = (uint32_t)(((2*kk + ((lane>>3)&1)) ^ l7) << 4);
    }
    return f;
}
__device__ __forceinline__ void mma_stage(uint32_t Ab, uint32_t Bb,
                                          const FragCtx& f, float c[2][8][4])
{
    #pragma unroll
    for (int kk = 0; kk < 4; kk++) {
        uint32_t a0[4], a1[4];
        ldsm4(a0, Ab + f.aoff + f.axor[kk]);
        ldsm4(a1, Ab + f.aoff + 2048u + f.axor[kk]);
        #pragma unroll
        for (int g = 0; g < 4; g++) {
            uint32_t bb[4];
            ldsm4(bb, Bb + f.boff + (uint32_t)g*2048u + f.bxor[kk]);
            MMA_F16(c[0][2*g],   a0, bb[0], bb[1]);
            MMA_F16(c[1][2*g],   a1, bb[0], bb[1]);
            MMA_F16(c[0][2*g+1], a0, bb[2], bb[3]);
            MMA_F16(c[1][2*g+1], a1, bb[2], bb[3]);
        }
    }
}

// ---------------- fp16 GEMM ----------------
template<int OUTHALF>
__global__ __launch_bounds__(256, 2) void hgemm_kernel(
    const __half* __restrict__ A, const __half* __restrict__ B,
    const float* __restrict__ bias, const float* __restrict__ res,
    void* __restrict__ Cout, int N)
{
    extern __shared__ __align__(16) char dsm[];
    __shared__ float sbias[128];
    const int tid = threadIdx.x, lane = tid & 31, wid = tid >> 5;
    const int wm = wid & 3, wn = wid >> 2;
    const int bx = blockIdx.x, by = blockIdx.y;

    if (tid < 128) sbias[tid] = bias ? bias[bx*128 + tid] : 0.f;

    const int mrow = tid >> 1;
    const int q0 = (tid & 1) * 4;
    const __half* asrc = A + ((size_t)(by*128 + mrow))*256;
    const __half* bsrc = B + ((size_t)(bx*128 + mrow))*256;
    const uint32_t sb = smem_u32(dsm);
    const uint32_t dst = sb + (uint32_t)mrow*128u;
    FragCtx f = make_frag_ctx(lane, wm, wn);

    float c[2][8][4];
    #pragma unroll
    for (int t = 0; t < 2; t++)
        #pragma unroll
        for (int j = 0; j < 8; j++)
            #pragma unroll
            for (int q = 0; q < 4; q++) c[t][j][q] = 0.f;

    auto load_st = [&](int s) {
        uint32_t base = (uint32_t)(s % 3) * 32768u;
        #pragma unroll
        for (int q = q0; q < q0 + 4; q++) {
            uint32_t sw = (uint32_t)((q ^ (mrow & 7)) << 4);
            cp16(dst + base + sw, asrc + s*64 + q*8);
            cp16(dst + base + 16384u + sw, bsrc + s*64 + q*8);
        }
    };
    load_st(0); CP_COMMIT();
    load_st(1); CP_COMMIT();
    #pragma unroll
    for (int k = 0; k < 4; k++) {
        CP_WAIT1();
        __syncthreads();
        if (k + 2 < 4) load_st(k + 2);
        CP_COMMIT();
        uint32_t Ab = sb + (uint32_t)(k % 3)*32768u;
        mma_stage(Ab, Ab + 16384u, f, c);
    }
    __syncthreads();

    float* Cb = (float*)dsm;   // 128 x 132
    const int r0 = lane >> 2, c0 = lane & 3;
    #pragma unroll
    for (int t = 0; t < 2; t++) {
        int row = wm*32 + t*16 + r0;
        #pragma unroll
        for (int t2 = 0; t2 < 8; t2++) {
            int col = wn*64 + t2*8 + (c0 << 1);
            Cb[row*132 + col]       = c[t][t2][0] + sbias[col];
            Cb[row*132 + col + 1]   = c[t][t2][1] + sbias[col+1];
            Cb[(row+8)*132 + col]   = c[t][t2][2] + sbias[col];
            Cb[(row+8)*132 + col+1] = c[t][t2][3] + sbias[col+1];
        }
    }
    __syncthreads();

    const int m = tid >> 1, ch = (tid & 1) << 6;
    size_t goff = ((size_t)(by*128 + m))*N + bx*128 + ch;
    if (OUTHALF) {
        __half* Ch = (__half*)Cout;
        #pragma unroll
        for (int j8 = 0; j8 < 8; j8++) {
            const float* p = &Cb[m*132 + ch + j8*8];
            __half2 h0 = __floats2half2_rn(p[0], p[1]);
            __half2 h1 = __floats2half2_rn(p[2], p[3]);
            __half2 h2 = __floats2half2_rn(p[4], p[5]);
            __half2 h3 = __floats2half2_rn(p[6], p[7]);
            uint4 u;
            u.x = *(uint32_t*)&h0; u.y = *(uint32_t*)&h1;
            u.z = *(uint32_t*)&h2; u.w = *(uint32_t*)&h3;
            *(uint4*)(Ch + goff + j8*8) = u;
        }
    } else {
        float* Cf = (float*)Cout;
        #pragma unroll
        for (int j4 = 0; j4 < 16; j4++) {
            float4 v = *(const float4*)&Cb[m*132 + ch + j4*4];
            if (res) {
                float4 r = *(const float4*)(res + goff + j4*4);
                v.x += r.x; v.y += r.y; v.z += r.z; v.w += r.w;
            }
            *(float4*)(Cf + goff + j4*4) = v;
        }
    }
}

// ---------------- bias matrix precompute: [head][r:128][m:112] ----------------
__global__ void bmat_kernel(const float* __restrict__ btab, float* __restrict__ bm)
{
    int i = blockIdx.x*256 + threadIdx.x;
    if (i >= 4*128*112) return;
    int m = i % 112; int r = (i/112) & 127; int head = i / (112*128);
    float v = 0.f;
    if (r < 98) {
        if (m >= 98) v = -1e30f;
        else {
            int pd_r = r/49; int rr = r - pd_r*49; int ph_r = rr/7, pw_r = rr - ph_r*7;
            int pd_m = m/49; int mm = m - pd_m*49; int ph_m = mm/7, pw_m = mm - ph_m*7;
            int rpi = ((pd_r - pd_m + 1)*13 + (ph_r - ph_m + 6))*13 + (pw_r - pw_m + 6);
            v = btab[rpi*4 + head];
        }
    }
    bm[i] = v;
}

// ---------------- tensor-core attention ----------------
// block = (window, head); 8 warps; M pad 128 (warp = one m16 tile), N pad 112, HD=64.
__global__ __launch_bounds__(256) void attn_mma_kernel(
    const __half* __restrict__ qkv, const float* __restrict__ bmat,
    __half* __restrict__ out, int grid_mode)
{
    __shared__ __align__(16) __half Qs[128*64];
    __shared__ __align__(16) __half Ks[112*64];
    __shared__ __align__(16) __half Vs[112*64];
    __shared__ int ts[NTOK];

    const int tid = threadIdx.x, lane = tid & 31, warp = tid >> 5;
    const int wi = blockIdx.x, head = blockIdx.y;
    const int b = wi >> 8, wd = (wi>>6)&3, wh = (wi>>3)&7, ww = wi & 7;
    const int hoff = head << 6;

    if (tid < NTOK) {
        int pd = tid / 49; int r7 = tid - pd*49; int ph = r7 / 7, pw = r7 - ph*7;
        int d, h, w;
        if (grid_mode) { d = pd*4 + wd; h = ph*8 + wh; w = pw*8 + ww; }
        else           { d = wd*2 + pd; h = wh*7 + ph; w = ww*7 + pw; }
        ts[tid] = ((b*8 + d)*56 + h)*56 + w;
    }
    __syncthreads();

    // load Q (scaled, 128 rows), K, V (112 rows) into swizzled smem
    {
        const int row = tid >> 1;
        const int cb = (tid & 1) * 4;
        const __half2 sc2 = __floats2half2_rn(SCALE_Q, SCALE_Q);
        const uint4 z4 = make_uint4(0,0,0,0);
        size_t base = (row < 98) ? ((size_t)ts[row]*768 + hoff) : 0;
        #pragma unroll
        for (int cc = 0; cc < 4; cc++) {
            int c = cb + cc;
            int sw8 = (c ^ (row & 7)) * 8;
            uint4 vq = z4, vk = z4, vv = z4;
            if (row < 98) {
                vq = *(const uint4*)(qkv + base + c*8);
                vk = *(const uint4*)(qkv + base + 256 + c*8);
                vv = *(const uint4*)(qkv + base + 512 + c*8);
                __half2* hq = (__half2*)&vq;
                hq[0] = __hmul2(hq[0], sc2); hq[1] = __hmul2(hq[1], sc2);
                hq[2] = __hmul2(hq[2], sc2); hq[3] = __hmul2(hq[3], sc2);
            }
            *(uint4*)(Qs + row*64 + sw8) = vq;
            if (row < 112) {
                *(uint4*)(Ks + row*64 + sw8) = vk;
                *(uint4*)(Vs + row*64 + sw8) = vv;
            }
        }
    }
    __syncthreads();

    const uint32_t qb = smem_u32(Qs), kb = smem_u32(Ks), vb = smem_u32(Vs);
    const int l7 = lane & 7;

    // ---- S = Q K^T : c[14][4], warp rows = warp*16 .. +15 ----
    float c[14][4];
    #pragma unroll
    for (int t = 0; t < 14; t++)
        #pragma unroll
        for (int q = 0; q < 4; q++) c[t][q] = 0.f;

    const uint32_t a_base = qb + (uint32_t)((warp*16 + ((lane>>3)&1)*8 + l7) * 128);
    const uint32_t b_rowo = (uint32_t)((((lane>>4)&1)*8 + l7) * 128);
    #pragma unroll
    for (int kk = 0; kk < 4; kk++) {
        uint32_t a[4];
        ldsm4(a, a_base + (uint32_t)(((2*kk + (lane>>4)) ^ l7) << 4));
        uint32_t bx_ = (uint32_t)(((2*kk + ((lane>>3)&1)) ^ l7) << 4);
        #pragma unroll
        for (int g = 0; g < 7; g++) {
            uint32_t bb[4];
            ldsm4(bb, kb + (uint32_t)(g*2048) + b_rowo + bx_);
            MMA_F16(c[2*g],   a, bb[0], bb[1]);
            MMA_F16(c[2*g+1], a, bb[2], bb[3]);
        }
    }

    // ---- bias + softmax (register-resident) ----
    const int r_lo = warp*16 + (lane >> 2);
    const int r_hi = r_lo + 8;
    const int mcol = (lane & 3) * 2;
    const float* bm_lo = bmat + ((size_t)head*128 + r_lo)*112 + mcol;
    const float* bm_hi = bm_lo + 8*112;
    float mx_lo = -1e30f, mx_hi = -1e30f;
    #pragma unroll
    for (int t = 0; t < 14; t++) {
        c[t][0] += bm_lo[t*8];  c[t][1] += bm_lo[t*8 + 1];
        c[t][2] += bm_hi[t*8];  c[t][3] += bm_hi[t*8 + 1];
        mx_lo = fmaxf(mx_lo, fmaxf(c[t][0], c[t][1]));
        mx_hi = fmaxf(mx_hi, fmaxf(c[t][2], c[t][3]));
    }
    #pragma unroll
    for (int o = 1; o <= 2; o <<= 1) {
        mx_lo = fmaxf(mx_lo, __shfl_xor_sync(0xffffffffu, mx_lo, o));
        mx_hi = fmaxf(mx_hi, __shfl_xor_sync(0xffffffffu, mx_hi, o));
    }
    float sum_lo = 0.f, sum_hi = 0.f;
    #pragma unroll
    for (int t = 0; t < 14; t++) {
        c[t][0] = __expf(c[t][0] - mx_lo); sum_lo += c[t][0];
        c[t][1] = __expf(c[t][1] - mx_lo); sum_lo += c[t][1];
        c[t][2] = __expf(c[t][2] - mx_hi); sum_hi += c[t][2];
        c[t][3] = __expf(c[t][3] - mx_hi); sum_hi += c[t][3];
    }
    #pragma unroll
    for (int o = 1; o <= 2; o <<= 1) {
        sum_lo += __shfl_xor_sync(0xffffffffu, sum_lo, o);
        sum_hi += __shfl_xor_sync(0xffffffffu, sum_hi, o);
    }
    const float inv_lo = 1.f / sum_lo, inv_hi = 1.f / sum_hi;

    // pack P fragments: S C-frag -> A-frag (k = previous n)
    uint32_t ap[7][4];
    #pragma unroll
    for (int j = 0; j < 7; j++) {
        __half2 h;
        h = __floats2half2_rn(c[2*j][0]*inv_lo,   c[2*j][1]*inv_lo);   ap[j][0] = *(uint32_t*)&h;
        h = __floats2half2_rn(c[2*j][2]*inv_hi,   c[2*j][3]*inv_hi);   ap[j][1] = *(uint32_t*)&h;
        h = __floats2half2_rn(c[2*j+1][0]*inv_lo, c[2*j+1][1]*inv_lo); ap[j][2] = *(uint32_t*)&h;
        h = __floats2half2_rn(c[2*j+1][2]*inv_hi, c[2*j+1][3]*inv_hi); ap[j][3] = *(uint32_t*)&h;
    }

    // ---- O = P V : V via ldmatrix.trans ----
    float c2[8][4];
    #pragma unroll
    for (int t = 0; t < 8; t++)
        #pragma unroll
        for (int q = 0; q < 4; q++) c2[t][q] = 0.f;

    #pragma unroll
    for (int j = 0; j < 7; j++) {
        int vrow = j*16 + l7 + 8*((lane>>3)&1);
        uint32_t vbase = vb + (uint32_t)(vrow * 128);
        #pragma unroll
        for (int g = 0; g < 4; g++) {
            uint32_t bb[4];
            ldsm4t(bb, vbase + (uint32_t)((((2*g) + (lane>>4)) ^ (vrow & 7)) << 4));
            MMA_F16(c2[2*g],   ap[j], bb[0], bb[1]);
            MMA_F16(c2[2*g+1], ap[j], bb[2], bb[3]);
        }
    }

    // ---- store rows < 98 ----
    if (r_lo < 98) {
        __half* op = out + (size_t)ts[r_lo]*256 + hoff;
        #pragma unroll
        for (int t2 = 0; t2 < 8; t2++) {
            __half2 h = __floats2half2_rn(c2[t2][0], c2[t2][1]);
            *(__half2*)(op + t2*8 + mcol) = h;
        }
    }
    if (r_hi < 98) {
        __half* op = out + (size_t)ts[r_hi]*256 + hoff;
        #pragma unroll
        for (int t2 = 0; t2 < 8; t2++) {
            __half2 h = __floats2half2_rn(c2[t2][2], c2[t2][3]);
            *(__half2*)(op + t2*8 + mcol) = h;
        }
    }
}

// ---------------- s = input + y (fp32 NCDHW) + padded half s2 -> Xa ----------------
__global__ __launch_bounds__(256) void add_s_kernel(
    const float* __restrict__ in, const float* __restrict__ y,
    float* __restrict__ s, __half* __restrict__ Xa)
{
    __shared__ float sm[256][33];
    int b0 = blockIdx.x * 32;
    for (int i = threadIdx.x; i < 32*256; i += 256) {
        int tk = i >> 8, c = i & 255;
        sm[c][tk] = y[(size_t)(b0 + tk)*256 + c];
    }
    __syncthreads();
    int b = b0 / SP; int sp0 = b0 % SP;
    for (int i = threadIdx.x; i < 32*256; i += 256) {
        int c = i >> 5, k = i & 31;
        size_t gi = ((size_t)b*256 + c)*SP + sp0 + k;
        float v = in[gi] + sm[c][k];
        s[gi] = v;
        sm[c][k] = v;
    }
    __syncthreads();
    for (int i = threadIdx.x; i < 32*128; i += 256) {
        int tok = i >> 7, ci = i & 127;
        int sp = sp0 + tok;
        int d = sp / 3136; int r = sp - d*3136; int h = r / 56, w = r - h*56;
        int pad = (d+1)*PDH + (h+1)*58 + (w+1);
        Xa[((size_t)b*PAD_SP + pad)*128 + ci] = __float2half_rn(sm[128+ci][tok]);
    }
}

// ---------------- conv weight transform ----------------
__global__ void wt2_kernel(const float* __restrict__ w, __half* __restrict__ o)
{
    int i = blockIdx.x*256 + threadIdx.x;
    if (i >= 27*128*128) return;
    int ci = i & 127; int r = i >> 7; int co = r & 127; int tap = r >> 7;
    o[i] = __float2half_rn(w[(co*128 + ci)*27 + tap]);
}

// ---------------- fp16 implicit-GEMM conv ----------------
__global__ __launch_bounds__(256, 2) void conv_mma_kernel(
    const __half* __restrict__ Xin, const __half* __restrict__ w2,
    const float* __restrict__ bias, const float* __restrict__ res,
    float* __restrict__ outN, __half* __restrict__ outX, int leaky)
{
    extern __shared__ __align__(16) char dsm[];
    __shared__ float sbias[128];

    const int tid = threadIdx.x, lane = tid & 31, wid = tid >> 5;
    const int wm = wid & 3, wn = wid >> 2;
    const int bx = blockIdx.x;
    const int b = bx / 196;
    const int spb = (bx % 196) * 128;

    if (tid < 128) sbias[tid] = bias[tid];

    const int mrow = tid >> 1;
    const int q0 = (tid & 1) * 4;
    int sp_c = spb + mrow;
    int d_c = sp_c / 3136; int r_c = sp_c - d_c*3136; int h_c = r_c / 56, w_c = r_c - h_c*56;
    const int padrow = d_c*PDH + h_c*58 + w_c;
    const __half* XinB = Xin + (size_t)b * PAD_SP * 128;
    const uint32_t sb = smem_u32(dsm);
    const uint32_t dst = sb + (uint32_t)mrow*128u;
    FragCtx f = make_frag_ctx(lane, wm, wn);

    float c[2][8][4];
    #pragma unroll
    for (int t = 0; t < 2; t++)
        #pragma unroll
        for (int j = 0; j < 8; j++)
            #pragma unroll
            for (int q = 0; q < 4; q++) c[t][j][q] = 0.f;

    const int NST = 54;
    auto load_st = [&](int s) {
        int tap = s >> 1, kh64 = (s & 1) * 64;
        int kd = tap / 9; int rem = tap - kd*9; int kh = rem / 3, kw = rem - kh*3;
        int toff = kd*PDH + kh*58 + kw;
        uint32_t base = (uint32_t)(s % 3) * 32768u;
        const __half* ga = XinB + (size_t)(padrow + toff)*128 + kh64;
        const __half* gb = w2 + ((size_t)tap*128 + mrow)*128 + kh64;
        #pragma unroll
        for (int q = q0; q < q0 + 4; q++) {
            uint32_t sw = (uint32_t)((q ^ (mrow & 7)) << 4);
            cp16(dst + base + sw, ga + q*8);
            cp16(dst + base + 16384u + sw, gb + q*8);
        }
    };
    load_st(0); CP_COMMIT();
    load_st(1); CP_COMMIT();
    for (int k = 0; k < NST; k++) {
        CP_WAIT1();
        __syncthreads();
        if (k + 2 < NST) load_st(k + 2);
        CP_COMMIT();
        uint32_t Ab = sb + (uint32_t)(k % 3)*32768u;
        mma_stage(Ab, Ab + 16384u, f, c);
    }
    __syncthreads();

    float* Cb = (float*)dsm;   // 128 x 132
    const int r0 = lane >> 2, c0 = lane & 3;
    #pragma unroll
    for (int t = 0; t < 2; t++) {
        int row = wm*32 + t*16 + r0;
        #pragma unroll
        for (int t2 = 0; t2 < 8; t2++) {
            int col = wn*64 + t2*8 + (c0 << 1);
            float b0s = sbias[col], b1s = sbias[col+1];
            float v0 = c[t][t2][0] + b0s;
            float v1 = c[t][t2][1] + b1s;
            float v2 = c[t][t2][2] + b0s;
            float v3 = c[t][t2][3] + b1s;
            if (leaky) {
                v0 = (v0 >= 0.f) ? v0 : 0.01f*v0;
                v1 = (v1 >= 0.f) ? v1 : 0.01f*v1;
                v2 = (v2 >= 0.f) ? v2 : 0.01f*v2;
                v3 = (v3 >= 0.f) ? v3 : 0.01f*v3;
            }
            Cb[row*132 + col]       = v0;
            Cb[row*132 + col + 1]   = v1;
            Cb[(row+8)*132 + col]   = v2;
            Cb[(row+8)*132 + col+1] = v3;
        }
    }
    __syncthreads();

    if (res) {
        int co = tid >> 1, mh = (tid & 1) << 6;
        const float* rp = res + (size_t)b*256*SP + (size_t)co*SP + spb + mh;
        #pragma unroll
        for (int j4 = 0; j4 < 16; j4++) {
            float4 r4 = *(const float4*)(rp + j4*4);
            Cb[(mh + j4*4 + 0)*132 + co] += r4.x;
            Cb[(mh + j4*4 + 1)*132 + co] += r4.y;
            Cb[(mh + j4*4 + 2)*132 + co] += r4.z;
            Cb[(mh + j4*4 + 3)*132 + co] += r4.w;
        }
        __syncthreads();
    }

    if (outX) {
        int m = tid >> 1, ch = (tid & 1) << 6;
        int sp = spb + m; int d = sp / 3136; int r = sp - d*3136; int h = r / 56, w = r - h*56;
        size_t po = (size_t)(d+1)*PDH + (size_t)(h+1)*58 + (w+1);
        __half* xp = outX + ((size_t)b*PAD_SP + po)*128 + ch;
        #pragma unroll
        for (int j8 = 0; j8 < 8; j8++) {
            const float* p = &Cb[m*132 + ch + j8*8];
            __half2 h0 = __floats2half2_rn(p[0], p[1]);
            __half2 h1 = __floats2half2_rn(p[2], p[3]);
            __half2 h2 = __floats2half2_rn(p[4], p[5]);
            __half2 h3 = __floats2half2_rn(p[6], p[7]);
            uint4 u;
            u.x = *(uint32_t*)&h0; u.y = *(uint32_t*)&h1;
            u.z = *(uint32_t*)&h2; u.w = *(uint32_t*)&h3;
            *(uint4*)(xp + j8*8) = u;
        }
    }
    if (outN) {
        int co = tid >> 1, mh = (tid & 1) << 6;
        float* op = outN + (size_t)b*256*SP + (size_t)co*SP + spb + mh;
        #pragma unroll
        for (int j4 = 0; j4 < 16; j4++) {
            float4 o;
            o.x = Cb[(mh + j4*4 + 0)*132 + co];
            o.y = Cb[(mh + j4*4 + 1)*132 + co];
            o.z = Cb[(mh + j4*4 + 2)*132 + co];
            o.w = Cb[(mh + j4*4 + 3)*132 + co];
            *(float4*)(op + j4*4) = o;
        }
    }
}

// ---------------- launcher ----------------
extern "C" void kernel_launch(void* const* d_in, const int* in_sizes, int n_in,
                              void* d_out, int out_size)
{
    (void)in_sizes; (void)n_in; (void)out_size;
    const float* input  = (const float*)d_in[0];
    const float* n1w    = (const float*)d_in[1];
    const float* n1b    = (const float*)d_in[2];
    const float* n2w    = (const float*)d_in[3];
    const float* n2b    = (const float*)d_in[4];
    const float* wqkv   = (const float*)d_in[5];
    const float* wprojw = (const float*)d_in[6];
    const float* wprojb = (const float*)d_in[7];
    const float* wbias  = (const float*)d_in[8];
    const float* gqkv   = (const float*)d_in[9];
    const float* gprojw = (const float*)d_in[10];
    const float* gprojb = (const float*)d_in[11];
    const float* gbias  = (const float*)d_in[12];
    const float* f1c1w  = (const float*)d_in[13];
    const float* f1c1b  = (const float*)d_in[14];
    const float* f1c2w  = (const float*)d_in[15];
    const float* f1c2b  = (const float*)d_in[16];
    const float* g1c1w  = (const float*)d_in[17];
    const float* g1c1b  = (const float*)d_in[18];
    const float* g1c2w  = (const float*)d_in[19];
    const float* g1c2b  = (const float*)d_in[20];
    float* out = (float*)d_out;

    __half *xh, *qkvh, *atnh, *Xa, *Xb, *w2h, *wqkvh, *gqkvh, *wprjh, *gprjh;
    float *xw, *y, *s, *bmat;
    cudaGetSymbolAddress((void**)&xh,    g_xh);
    cudaGetSymbolAddress((void**)&qkvh,  g_qkvh);
    cudaGetSymbolAddress((void**)&atnh,  g_atnh);
    cudaGetSymbolAddress((void**)&xw,    g_xw);
    cudaGetSymbolAddress((void**)&y,     g_y);
    cudaGetSymbolAddress((void**)&s,     g_s);
    cudaGetSymbolAddress((void**)&Xa,    g_Xa);
    cudaGetSymbolAddress((void**)&Xb,    g_Xb);
    cudaGetSymbolAddress((void**)&w2h,   g_w2h);
    cudaGetSymbolAddress((void**)&wqkvh, g_wqkvh);
    cudaGetSymbolAddress((void**)&gqkvh, g_gqkvh);
    cudaGetSymbolAddress((void**)&wprjh, g_wprjh);
    cudaGetSymbolAddress((void**)&gprjh, g_gprjh);
    cudaGetSymbolAddress((void**)&bmat,  g_bmat);

    const int TSMEM = 3 * 32768;
    cudaFuncSetAttribute(hgemm_kernel<1>, cudaFuncAttributeMaxDynamicSharedMemorySize, TSMEM);
    cudaFuncSetAttribute(hgemm_kernel<0>, cudaFuncAttributeMaxDynamicSharedMemorySize, TSMEM);
    cudaFuncSetAttribute(conv_mma_kernel, cudaFuncAttributeMaxDynamicSharedMemorySize, TSMEM);

    // weight conversions
    f2h_kernel<<<768, 256>>>(wqkv, wqkvh, 768*256);
    f2h_kernel<<<768, 256>>>(gqkv, gqkvh, 768*256);
    f2h_kernel<<<256, 256>>>(wprojw, wprjh, 256*256);
    f2h_kernel<<<256, 256>>>(gprojw, gprjh, 256*256);

    // window attention block
    ln_in_kernel<<<1792, 256>>>(input, n1w, n1b, xh);
    hgemm_kernel<1><<<dim3(6, 392), 256, TSMEM>>>(xh, wqkvh, nullptr, nullptr, qkvh, 768);
    bmat_kernel<<<224, 256>>>(wbias, bmat);
    attn_mma_kernel<<<dim3(512, 4), 256>>>(qkvh, bmat, atnh, 0);
    hgemm_kernel<0><<<dim3(2, 392), 256, TSMEM>>>(atnh, wprjh, wprojb, nullptr, xw, 256);
    // grid attention block
    ln_row_kernel<<<6272, 256>>>(xw, n2w, n2b, xh);
    hgemm_kernel<1><<<dim3(6, 392), 256, TSMEM>>>(xh, gqkvh, nullptr, nullptr, qkvh, 768);
    bmat_kernel<<<224, 256>>>(gbias, bmat);
    attn_mma_kernel<<<dim3(512, 4), 256>>>(qkvh, bmat, atnh, 1);
    hgemm_kernel<0><<<dim3(2, 392), 256, TSMEM>>>(atnh, gprjh, gprojb, xw, y, 256);
    add_s_kernel<<<1568, 256>>>(input, y, s, Xa);

    // conv chain
    wt2_kernel<<<1728, 256>>>(f1c1w, w2h);
    conv_mma_kernel<<<392, 256, TSMEM>>>(Xa, w2h, f1c1b, nullptr, nullptr, Xb, 1);
    wt2_kernel<<<1728, 256>>>(f1c2w, w2h);
    conv_mma_kernel<<<392, 256, TSMEM>>>(Xb, w2h, f1c2b, s, out, Xa, 0);
    wt2_kernel<<<1728, 256>>>(g1c1w, w2h);
    conv_mma_kernel<<<392, 256, TSMEM>>>(Xa, w2h, g1c1b, nullptr, nullptr, Xb, 1);
    wt2_kernel<<<1728, 256>>>(g1c2w, w2h);
    conv_mma_kernel<<<392, 256, TSMEM>>>(Xb, w2h, g1c2b, s + (size_t)128*SP,
                                         out + (size_t)128*SP, nullptr, 0);
}

// round 9
// speedup vs baseline: 3.3060x; 1.0327x over previous
#include <cuda_runtime.h>
#include <cuda_fp16.h>
#include <cstdint>
#include <cstddef>

// ---------------- problem constants ----------------
#define SP    25088          // 8*56*56
#define T_TOK 50176          // 2*SP
#define NTOK  98
#define SCALE_Q 0.125f
#define PAD_SP 33640         // 10*58*58
#define PDH    3364          // 58*58
#define W2SZ  (27*128*128)

// ---------------- scratch ----------------
__device__ __half g_xh  [(size_t)T_TOK*256];
__device__ __half g_qkvh[(size_t)T_TOK*768];
__device__ __half g_atnh[(size_t)T_TOK*256];
__device__ float  g_xw  [(size_t)T_TOK*256];
__device__ float  g_s   [(size_t)T_TOK*256];
__device__ __half g_Xa  [(size_t)2*PAD_SP*128];   // zero-init padding stays zero
__device__ __half g_Xb  [(size_t)2*PAD_SP*128];
__device__ __half g_w2h [(size_t)4*W2SZ];         // 4 conv weights [tap][co][ci]
__device__ __half g_wqkvh[768*256];
__device__ __half g_gqkvh[768*256];
__device__ __half g_wprjh[256*256];
__device__ __half g_gprjh[256*256];
__device__ float  g_bmat[(size_t)2*4*128*112];    // bias matrices [attn][head][r][m]

// ---------------- PTX helpers (sm_80-baseline only) ----------------
__device__ __forceinline__ uint32_t smem_u32(const void* p) {
    uint32_t a;
    asm("{ .reg .u64 t; cvta.to.shared.u64 t, %1; cvt.u32.u64 %0, t; }" : "=r"(a) : "l"(p));
    return a;
}
__device__ __forceinline__ void cp16(uint32_t s, const void* g) {
    asm volatile("cp.async.cg.shared.global [%0], [%1], 16;" :: "r"(s), "l"(g));
}
#define CP_COMMIT() asm volatile("cp.async.commit_group;" ::: "memory")
#define CP_WAIT1()  asm volatile("cp.async.wait_group 1;"  ::: "memory")

__device__ __forceinline__ void ldsm4(uint32_t* r, uint32_t a) {
    asm volatile("ldmatrix.sync.aligned.m8n8.x4.shared.b16 {%0,%1,%2,%3}, [%4];"
        : "=r"(r[0]), "=r"(r[1]), "=r"(r[2]), "=r"(r[3]) : "r"(a));
}
__device__ __forceinline__ void ldsm4t(uint32_t* r, uint32_t a) {
    asm volatile("ldmatrix.sync.aligned.m8n8.x4.trans.shared.b16 {%0,%1,%2,%3}, [%4];"
        : "=r"(r[0]), "=r"(r[1]), "=r"(r[2]), "=r"(r[3]) : "r"(a));
}
#define MMA_F16(c, a, b0, b1) \
    asm volatile("mma.sync.aligned.m16n8k16.row.col.f32.f16.f16.f32 " \
        "{%0,%1,%2,%3}, {%4,%5,%6,%7}, {%8,%9}, {%0,%1,%2,%3};" \
        : "+f"((c)[0]), "+f"((c)[1]), "+f"((c)[2]), "+f"((c)[3]) \
        : "r"((a)[0]), "r"((a)[1]), "r"((a)[2]), "r"((a)[3]), "r"(b0), "r"(b1))

// ---------------- all weight/bias prep in ONE kernel ----------------
__global__ __launch_bounds__(256) void prep_kernel(
    const float* __restrict__ wqkv, const float* __restrict__ gqkv,
    const float* __restrict__ wprj, const float* __restrict__ gprj,
    const float* __restrict__ c1w, const float* __restrict__ c2w,
    const float* __restrict__ c3w, const float* __restrict__ c4w,
    const float* __restrict__ wbias, const float* __restrict__ gbias,
    __half* __restrict__ wqkvh, __half* __restrict__ gqkvh,
    __half* __restrict__ wprjh, __half* __restrict__ gprjh,
    __half* __restrict__ w2h, float* __restrict__ bmat)
{
    int bx = blockIdx.x, tid = threadIdx.x;
    if (bx < 1536) {                       // qkv weights f2h: 2 x 768 blocks
        // NOTE: 768 is not a power of two -> explicit subtract (the &767 bug
        // left gqkvh rows 256..511 (grid K weights) as zeros).
        int j = (bx >= 768) ? (bx - 768) : bx;
        const float* s = (bx < 768) ? wqkv : gqkv;
        __half* d = (bx < 768) ? wqkvh : gqkvh;
        int i = j*256 + tid;
        d[i] = __float2half_rn(s[i]);
    } else if (bx < 2048) {                // proj weights f2h: 2 x 256 blocks
        const float* s = (bx < 1792) ? wprj : gprj;
        __half* d = (bx < 1792) ? wprjh : gprjh;
        int j = bx - 1536; if (j >= 256) j -= 256;
        int i = j*256 + tid;
        d[i] = __float2half_rn(s[i]);
    } else if (bx < 8960) {                // conv weight transform: 4 x 1728 blocks
        int seg = (bx - 2048) / 1728;
        const float* w = (seg == 0) ? c1w : (seg == 1) ? c2w : (seg == 2) ? c3w : c4w;
        __half* o = w2h + (size_t)seg * W2SZ;
        int i = ((bx - 2048) % 1728)*256 + tid;
        int ci = i & 127; int r = i >> 7; int co = r & 127; int tap = r >> 7;
        o[i] = __float2half_rn(w[(co*128 + ci)*27 + tap]);
    } else {                               // bias matrices: 2 x 224 blocks
        int seg = (bx - 8960) / 224;
        const float* bt = seg ? gbias : wbias;
        float* bm = bmat + (size_t)seg * 4*128*112;
        int i = ((bx - 8960) % 224)*256 + tid;
        int m = i % 112; int r = (i/112) & 127; int head = i / (112*128);
        float v = 0.f;
        if (r < 98) {
            if (m >= 98) v = -1e30f;
            else {
                int pd_r = r/49; int rr = r - pd_r*49; int ph_r = rr/7, pw_r = rr - ph_r*7;
                int pd_m = m/49; int mm = m - pd_m*49; int ph_m = mm/7, pw_m = mm - ph_m*7;
                int rpi = ((pd_r - pd_m + 1)*13 + (ph_r - ph_m + 6))*13 + (pw_r - pw_m + 6);
                v = bt[rpi*4 + head];
            }
        }
        bm[i] = v;
    }
}

// ---------------- LN kernels (output half) ----------------
__global__ __launch_bounds__(256) void ln_in_kernel(
    const float* __restrict__ in, const float* __restrict__ w,
    const float* __restrict__ b, __half* __restrict__ out)
{
    __shared__ float s[28][257];
    int bx = blockIdx.x;
    int wt = bx & 1; int tmp = bx >> 1;
    int h = tmp % 56; tmp /= 56;
    int d = tmp & 7; int bb = tmp >> 3;
    int w0 = wt * 28;
    size_t sp = ((size_t)d*56 + h)*56 + w0;
    const float* ib = in + (size_t)bb*256*SP + sp;
    for (int i = threadIdx.x; i < 28*256; i += 256) {
        int c = i / 28, ww_ = i - c*28;
        s[ww_][c] = ib[(size_t)c*SP + ww_];
    }
    __syncthreads();
    int warp = threadIdx.x >> 5, lane = threadIdx.x & 31;
    for (int tk = warp; tk < 28; tk += 8) {
        float s1 = 0.f, s2 = 0.f;
        #pragma unroll
        for (int j = 0; j < 8; j++) { float v = s[tk][lane + (j<<5)]; s1 += v; s2 += v*v; }
        #pragma unroll
        for (int o = 16; o; o >>= 1) {
            s1 += __shfl_xor_sync(0xffffffffu, s1, o);
            s2 += __shfl_xor_sync(0xffffffffu, s2, o);
        }
        float m = s1 * (1.f/256.f);
        float var = s2 * (1.f/256.f) - m*m;
        float iv = rsqrtf(var + 1e-5f);
        size_t t = (size_t)bb*SP + sp + tk;
        __half* orow = out + t*256;
        #pragma unroll
        for (int j = 0; j < 8; j++) {
            int c = lane + (j<<5);
            orow[c] = __float2half_rn((s[tk][c] - m) * iv * w[c] + b[c]);
        }
    }
}

__global__ __launch_bounds__(256) void ln_row_kernel(
    const float* __restrict__ in, const float* __restrict__ w,
    const float* __restrict__ b, __half* __restrict__ out)
{
    int t = blockIdx.x*8 + (threadIdx.x >> 5);
    int lane = threadIdx.x & 31;
    const float* row = in + (size_t)t*256;
    float v[8]; float s1 = 0.f, s2 = 0.f;
    #pragma unroll
    for (int j = 0; j < 8; j++) { v[j] = row[lane + (j<<5)]; s1 += v[j]; s2 += v[j]*v[j]; }
    #pragma unroll
    for (int o = 16; o; o >>= 1) {
        s1 += __shfl_xor_sync(0xffffffffu, s1, o);
        s2 += __shfl_xor_sync(0xffffffffu, s2, o);
    }
    float m = s1 * (1.f/256.f);
    float var = s2 * (1.f/256.f) - m*m;
    float iv = rsqrtf(var + 1e-5f);
    __half* orow = out + (size_t)t*256;
    #pragma unroll
    for (int j = 0; j < 8; j++) {
        int c = lane + (j<<5);
        orow[c] = __float2half_rn((v[j] - m) * iv * w[c] + b[c]);
    }
}

// ---------------- shared warp-MMA stage: 128x128 tile, BK=64 ----------------
struct FragCtx {
    uint32_t aoff;
    uint32_t boff;
    uint32_t axor[4];
    uint32_t bxor[4];
};
__device__ __forceinline__ FragCtx make_frag_ctx(int lane, int wm, int wn) {
    FragCtx f;
    int l7 = lane & 7;
    f.aoff = (uint32_t)((wm*32 + ((lane>>3)&1)*8 + l7) * 128);
    f.boff = (uint32_t)((wn*64 + ((lane>>4)&1)*8 + l7) * 128);
    #pragma unroll
    for (int kk = 0; kk < 4; kk++) {
        f.axor[kk] = (uint32_t)(((2*kk + (lane>>4)) ^ l7) << 4);
        f.bxor[kk] = (uint32_t)(((2*kk + ((lane>>3)&1)) ^ l7) << 4);
    }
    return f;
}
__device__ __forceinline__ void mma_stage(uint32_t Ab, uint32_t Bb,
                                          const FragCtx& f, float c[2][8][4])
{
    #pragma unroll
    for (int kk = 0; kk < 4; kk++) {
        uint32_t a0[4], a1[4];
        ldsm4(a0, Ab + f.aoff + f.axor[kk]);
        ldsm4(a1, Ab + f.aoff + 2048u + f.axor[kk]);
        #pragma unroll
        for (int g = 0; g < 4; g++) {
            uint32_t bb[4];
            ldsm4(bb, Bb + f.boff + (uint32_t)g*2048u + f.bxor[kk]);
            MMA_F16(c[0][2*g],   a0, bb[0], bb[1]);
            MMA_F16(c[1][2*g],   a1, bb[0], bb[1]);
            MMA_F16(c[0][2*g+1], a0, bb[2], bb[3]);
            MMA_F16(c[1][2*g+1], a1, bb[2], bb[3]);
        }
    }
}

// ---------------- shared mainloop body for 128x128 @ K=256 GEMM ----------------
__device__ __forceinline__ void hgemm_mainloop(
    const __half* asrc, const __half* bsrc, uint32_t sb, uint32_t dst,
    int q0, int mrow, const FragCtx& f, float c[2][8][4])
{
    auto load_st = [&](int s) {
        uint32_t base = (uint32_t)(s % 3) * 32768u;
        #pragma unroll
        for (int q = q0; q < q0 + 4; q++) {
            uint32_t sw = (uint32_t)((q ^ (mrow & 7)) << 4);
            cp16(dst + base + sw, asrc + s*64 + q*8);
            cp16(dst + base + 16384u + sw, bsrc + s*64 + q*8);
        }
    };
    load_st(0); CP_COMMIT();
    load_st(1); CP_COMMIT();
    #pragma unroll
    for (int k = 0; k < 4; k++) {
        CP_WAIT1();
        __syncthreads();
        if (k + 2 < 4) load_st(k + 2);
        CP_COMMIT();
        uint32_t Ab = sb + (uint32_t)(k % 3)*32768u;
        mma_stage(Ab, Ab + 16384u, f, c);
    }
    __syncthreads();
}

// ---------------- fp16 GEMM (plain): OUTHALF 1 -> C half, 0 -> C float (+res) --------
template<int OUTHALF>
__global__ __launch_bounds__(256, 2) void hgemm_kernel(
    const __half* __restrict__ A, const __half* __restrict__ B,
    const float* __restrict__ bias, const float* __restrict__ res,
    void* __restrict__ Cout, int N)
{
    extern __shared__ __align__(16) char dsm[];
    __shared__ float sbias[128];
    const int tid = threadIdx.x, lane = tid & 31, wid = tid >> 5;
    const int wm = wid & 3, wn = wid >> 2;
    const int bx = blockIdx.x, by = blockIdx.y;

    if (tid < 128) sbias[tid] = bias ? bias[bx*128 + tid] : 0.f;

    const int mrow = tid >> 1;
    const int q0 = (tid & 1) * 4;
    const uint32_t sb = smem_u32(dsm);
    FragCtx f = make_frag_ctx(lane, wm, wn);
    float c[2][8][4];
    #pragma unroll
    for (int t = 0; t < 2; t++)
        #pragma unroll
        for (int j = 0; j < 8; j++)
            #pragma unroll
            for (int q = 0; q < 4; q++) c[t][j][q] = 0.f;

    hgemm_mainloop(A + ((size_t)(by*128 + mrow))*256,
                   B + ((size_t)(bx*128 + mrow))*256,
                   sb, sb + (uint32_t)mrow*128u, q0, mrow, f, c);

    float* Cb = (float*)dsm;   // 128 x 132
    const int r0 = lane >> 2, c0 = lane & 3;
    #pragma unroll
    for (int t = 0; t < 2; t++) {
        int row = wm*32 + t*16 + r0;
        #pragma unroll
        for (int t2 = 0; t2 < 8; t2++) {
            int col = wn*64 + t2*8 + (c0 << 1);
            Cb[row*132 + col]       = c[t][t2][0] + sbias[col];
            Cb[row*132 + col + 1]   = c[t][t2][1] + sbias[col+1];
            Cb[(row+8)*132 + col]   = c[t][t2][2] + sbias[col];
            Cb[(row+8)*132 + col+1] = c[t][t2][3] + sbias[col+1];
        }
    }
    __syncthreads();

    const int m = tid >> 1, ch = (tid & 1) << 6;
    size_t goff = ((size_t)(by*128 + m))*N + bx*128 + ch;
    if (OUTHALF) {
        __half* Ch = (__half*)Cout;
        #pragma unroll
        for (int j8 = 0; j8 < 8; j8++) {
            const float* p = &Cb[m*132 + ch + j8*8];
            __half2 h0 = __floats2half2_rn(p[0], p[1]);
            __half2 h1 = __floats2half2_rn(p[2], p[3]);
            __half2 h2 = __floats2half2_rn(p[4], p[5]);
            __half2 h3 = __floats2half2_rn(p[6], p[7]);
            uint4 u;
            u.x = *(uint32_t*)&h0; u.y = *(uint32_t*)&h1;
            u.z = *(uint32_t*)&h2; u.w = *(uint32_t*)&h3;
            *(uint4*)(Ch + goff + j8*8) = u;
        }
    } else {
        float* Cf = (float*)Cout;
        #pragma unroll
        for (int j4 = 0; j4 < 16; j4++) {
            float4 v = *(const float4*)&Cb[m*132 + ch + j4*4];
            if (res) {
                float4 r = *(const float4*)(res + goff + j4*4);
                v.x += r.x; v.y += r.y; v.z += r.z; v.w += r.w;
            }
            *(float4*)(Cf + goff + j4*4) = v;
        }
    }
}

// ---------------- fused grid-proj: y = A@B^T + bias + xw; s = input + y; Xa = half(s2)
__global__ __launch_bounds__(256, 2) void hgemm_fuse_kernel(
    const __half* __restrict__ A, const __half* __restrict__ B,
    const float* __restrict__ bias, const float* __restrict__ xw,
    const float* __restrict__ input, float* __restrict__ s,
    __half* __restrict__ Xa)
{
    extern __shared__ __align__(16) char dsm[];
    __shared__ float sbias[128];
    const int tid = threadIdx.x, lane = tid & 31, wid = tid >> 5;
    const int wm = wid & 3, wn = wid >> 2;
    const int bx = blockIdx.x, by = blockIdx.y;

    if (tid < 128) sbias[tid] = bias[bx*128 + tid];

    const int mrow = tid >> 1;
    const int q0 = (tid & 1) * 4;
    const uint32_t sb = smem_u32(dsm);
    FragCtx f = make_frag_ctx(lane, wm, wn);
    float c[2][8][4];
    #pragma unroll
    for (int t = 0; t < 2; t++)
        #pragma unroll
        for (int j = 0; j < 8; j++)
            #pragma unroll
            for (int q = 0; q < 4; q++) c[t][j][q] = 0.f;

    hgemm_mainloop(A + ((size_t)(by*128 + mrow))*256,
                   B + ((size_t)(bx*128 + mrow))*256,
                   sb, sb + (uint32_t)mrow*128u, q0, mrow, f, c);

    float* Cb = (float*)dsm;   // 128 x 132, rows = tokens, cols = local chan
    const int r0 = lane >> 2, c0 = lane & 3;
    #pragma unroll
    for (int t = 0; t < 2; t++) {
        int row = wm*32 + t*16 + r0;
        #pragma unroll
        for (int t2 = 0; t2 < 8; t2++) {
            int col = wn*64 + t2*8 + (c0 << 1);
            Cb[row*132 + col]       = c[t][t2][0] + sbias[col];
            Cb[row*132 + col + 1]   = c[t][t2][1] + sbias[col+1];
            Cb[(row+8)*132 + col]   = c[t][t2][2] + sbias[col];
            Cb[(row+8)*132 + col+1] = c[t][t2][3] + sbias[col+1];
        }
    }
    __syncthreads();

    // phase A (token-major): y = Cb + xw
    const int m = tid >> 1, ch = (tid & 1) << 6;
    {
        size_t goff = ((size_t)(by*128 + m))*256 + bx*128 + ch;
        #pragma unroll
        for (int j4 = 0; j4 < 16; j4++) {
            float4 r = *(const float4*)(xw + goff + j4*4);
            float* p = &Cb[m*132 + ch + j4*4];
            p[0] += r.x; p[1] += r.y; p[2] += r.z; p[3] += r.w;
        }
    }
    __syncthreads();

    // phase B (chan-major, coalesced NCDHW): s = input + y; Cb <- s
    {
        const int co = tid >> 1, mh = (tid & 1) << 6;
        const int tok0 = by*128;
        const int b = tok0 / SP, sp0 = tok0 % SP;
        size_t gbase = (size_t)b*256*SP + (size_t)(bx*128 + co)*SP + sp0 + mh;
        #pragma unroll
        for (int j4 = 0; j4 < 16; j4++) {
            float4 iv = *(const float4*)(input + gbase + j4*4);
            float* p0 = &Cb[(mh + j4*4 + 0)*132 + co];
            float* p1 = &Cb[(mh + j4*4 + 1)*132 + co];
            float* p2 = &Cb[(mh + j4*4 + 2)*132 + co];
            float* p3 = &Cb[(mh + j4*4 + 3)*132 + co];
            float v0 = iv.x + *p0, v1 = iv.y + *p1, v2 = iv.z + *p2, v3 = iv.w + *p3;
            *p0 = v0; *p1 = v1; *p2 = v2; *p3 = v3;
            float4 o = make_float4(v0, v1, v2, v3);
            *(float4*)(s + gbase + j4*4) = o;
        }
    }
    __syncthreads();

    // phase C (token-major): Xa = half(s2) for channels 128..255 (bx==1)
    if (bx == 1) {
        const int tok = by*128 + m;
        const int b = tok / SP;
        int sp = tok % SP;
        int d = sp / 3136; int r = sp - d*3136; int h = r / 56, w = r - h*56;
        size_t po = (size_t)(d+1)*PDH + (size_t)(h+1)*58 + (w+1);
        __half* xp = Xa + ((size_t)b*PAD_SP + po)*128 + ch;
        #pragma unroll
        for (int j8 = 0; j8 < 8; j8++) {
            const float* p = &Cb[m*132 + ch + j8*8];
            __half2 h0 = __floats2half2_rn(p[0], p[1]);
            __half2 h1 = __floats2half2_rn(p[2], p[3]);
            __half2 h2 = __floats2half2_rn(p[4], p[5]);
            __half2 h3 = __floats2half2_rn(p[6], p[7]);
            uint4 u;
            u.x = *(uint32_t*)&h0; u.y = *(uint32_t*)&h1;
            u.z = *(uint32_t*)&h2; u.w = *(uint32_t*)&h3;
            *(uint4*)(xp + j8*8) = u;
        }
    }
}

// ---------------- tensor-core attention (M pad 112, 7 compute warps) ----------------
__global__ __launch_bounds__(256) void attn_mma_kernel(
    const __half* __restrict__ qkv, const float* __restrict__ bmat,
    __half* __restrict__ out, int grid_mode)
{
    __shared__ __align__(16) __half Qs[112*64];
    __shared__ __align__(16) __half Ks[112*64];
    __shared__ __align__(16) __half Vs[112*64];
    __shared__ int ts[NTOK];

    const int tid = threadIdx.x, lane = tid & 31, warp = tid >> 5;
    const int wi = blockIdx.x, head = blockIdx.y;
    const int b = wi >> 8, wd = (wi>>6)&3, wh = (wi>>3)&7, ww = wi & 7;
    const int hoff = head << 6;

    if (tid < NTOK) {
        int pd = tid / 49; int r7 = tid - pd*49; int ph = r7 / 7, pw = r7 - ph*7;
        int d, h, w;
        if (grid_mode) { d = pd*4 + wd; h = ph*8 + wh; w = pw*8 + ww; }
        else           { d = wd*2 + pd; h = wh*7 + ph; w = ww*7 + pw; }
        ts[tid] = ((b*8 + d)*56 + h)*56 + w;
    }
    __syncthreads();

    {
        const int row = tid >> 1;
        const int cb = (tid & 1) * 4;
        const __half2 sc2 = __floats2half2_rn(SCALE_Q, SCALE_Q);
        const uint4 z4 = make_uint4(0,0,0,0);
        if (row < 112) {
            size_t base = (row < 98) ? ((size_t)ts[row]*768 + hoff) : 0;
            #pragma unroll
            for (int cc = 0; cc < 4; cc++) {
                int c = cb + cc;
                int sw8 = (c ^ (row & 7)) * 8;
                uint4 vq = z4, vk = z4, vv = z4;
                if (row < 98) {
                    vq = *(const uint4*)(qkv + base + c*8);
                    vk = *(const uint4*)(qkv + base + 256 + c*8);
                    vv = *(const uint4*)(qkv + base + 512 + c*8);
                    __half2* hq = (__half2*)&vq;
                    hq[0] = __hmul2(hq[0], sc2); hq[1] = __hmul2(hq[1], sc2);
                    hq[2] = __hmul2(hq[2], sc2); hq[3] = __hmul2(hq[3], sc2);
                }
                *(uint4*)(Qs + row*64 + sw8) = vq;
                *(uint4*)(Ks + row*64 + sw8) = vk;
                *(uint4*)(Vs + row*64 + sw8) = vv;
            }
        }
    }
    __syncthreads();

    if (warp < 7) {
        const uint32_t qb = smem_u32(Qs), kb = smem_u32(Ks), vb = smem_u32(Vs);
        const int l7 = lane & 7;

        float c[14][4];
        #pragma unroll
        for (int t = 0; t < 14; t++)
            #pragma unroll
            for (int q = 0; q < 4; q++) c[t][q] = 0.f;

        const uint32_t a_base = qb + (uint32_t)((warp*16 + ((lane>>3)&1)*8 + l7) * 128);
        const uint32_t b_rowo = (uint32_t)((((lane>>4)&1)*8 + l7) * 128);
        #pragma unroll
        for (int kk = 0; kk < 4; kk++) {
            uint32_t a[4];
            ldsm4(a, a_base + (uint32_t)(((2*kk + (lane>>4)) ^ l7) << 4));
            uint32_t bx_ = (uint32_t)(((2*kk + ((lane>>3)&1)) ^ l7) << 4);
            #pragma unroll
            for (int g = 0; g < 7; g++) {
                uint32_t bb[4];
                ldsm4(bb, kb + (uint32_t)(g*2048) + b_rowo + bx_);
                MMA_F16(c[2*g],   a, bb[0], bb[1]);
                MMA_F16(c[2*g+1], a, bb[2], bb[3]);
            }
        }

        const int r_lo = warp*16 + (lane >> 2);
        const int r_hi = r_lo + 8;
        const int mcol = (lane & 3) * 2;
        const float* bm_lo = bmat + ((size_t)head*128 + r_lo)*112 + mcol;
        const float* bm_hi = bm_lo + 8*112;
        float mx_lo = -1e30f, mx_hi = -1e30f;
        #pragma unroll
        for (int t = 0; t < 14; t++) {
            c[t][0] += bm_lo[t*8];  c[t][1] += bm_lo[t*8 + 1];
            c[t][2] += bm_hi[t*8];  c[t][3] += bm_hi[t*8 + 1];
            mx_lo = fmaxf(mx_lo, fmaxf(c[t][0], c[t][1]));
            mx_hi = fmaxf(mx_hi, fmaxf(c[t][2], c[t][3]));
        }
        #pragma unroll
        for (int o = 1; o <= 2; o <<= 1) {
            mx_lo = fmaxf(mx_lo, __shfl_xor_sync(0xffffffffu, mx_lo, o));
            mx_hi = fmaxf(mx_hi, __shfl_xor_sync(0xffffffffu, mx_hi, o));
        }
        float sum_lo = 0.f, sum_hi = 0.f;
        #pragma unroll
        for (int t = 0; t < 14; t++) {
            c[t][0] = __expf(c[t][0] - mx_lo); sum_lo += c[t][0];
            c[t][1] = __expf(c[t][1] - mx_lo); sum_lo += c[t][1];
            c[t][2] = __expf(c[t][2] - mx_hi); sum_hi += c[t][2];
            c[t][3] = __expf(c[t][3] - mx_hi); sum_hi += c[t][3];
        }
        #pragma unroll
        for (int o = 1; o <= 2; o <<= 1) {
            sum_lo += __shfl_xor_sync(0xffffffffu, sum_lo, o);
            sum_hi += __shfl_xor_sync(0xffffffffu, sum_hi, o);
        }
        const float inv_lo = 1.f / sum_lo, inv_hi = 1.f / sum_hi;

        uint32_t ap[7][4];
        #pragma unroll
        for (int j = 0; j < 7; j++) {
            __half2 h;
            h = __floats2half2_rn(c[2*j][0]*inv_lo,   c[2*j][1]*inv_lo);   ap[j][0] = *(uint32_t*)&h;
            h = __floats2half2_rn(c[2*j][2]*inv_hi,   c[2*j][3]*inv_hi);   ap[j][1] = *(uint32_t*)&h;
            h = __floats2half2_rn(c[2*j+1][0]*inv_lo, c[2*j+1][1]*inv_lo); ap[j][2] = *(uint32_t*)&h;
            h = __floats2half2_rn(c[2*j+1][2]*inv_hi, c[2*j+1][3]*inv_hi); ap[j][3] = *(uint32_t*)&h;
        }

        float c2[8][4];
        #pragma unroll
        for (int t = 0; t < 8; t++)
            #pragma unroll
            for (int q = 0; q < 4; q++) c2[t][q] = 0.f;

        #pragma unroll
        for (int j = 0; j < 7; j++) {
            int vrow = j*16 + l7 + 8*((lane>>3)&1);
            uint32_t vbase = vb + (uint32_t)(vrow * 128);
            #pragma unroll
            for (int g = 0; g < 4; g++) {
                uint32_t bb[4];
                ldsm4t(bb, vbase + (uint32_t)((((2*g) + (lane>>4)) ^ (vrow & 7)) << 4));
                MMA_F16(c2[2*g],   ap[j], bb[0], bb[1]);
                MMA_F16(c2[2*g+1], ap[j], bb[2], bb[3]);
            }
        }

        if (r_lo < 98) {
            __half* op = out + (size_t)ts[r_lo]*256 + hoff;
            #pragma unroll
            for (int t2 = 0; t2 < 8; t2++) {
                __half2 h = __floats2half2_rn(c2[t2][0], c2[t2][1]);
                *(__half2*)(op + t2*8 + mcol) = h;
            }
        }
        if (r_hi < 98) {
            __half* op = out + (size_t)ts[r_hi]*256 + hoff;
            #pragma unroll
            for (int t2 = 0; t2 < 8; t2++) {
                __half2 h = __floats2half2_rn(c2[t2][2], c2[t2][3]);
                *(__half2*)(op + t2*8 + mcol) = h;
            }
        }
    }
}

// ---------------- fp16 implicit-GEMM conv ----------------
__global__ __launch_bounds__(256, 2) void conv_mma_kernel(
    const __half* __restrict__ Xin, const __half* __restrict__ w2,
    const float* __restrict__ bias, const float* __restrict__ res,
    float* __restrict__ outN, __half* __restrict__ outX, int leaky)
{
    extern __shared__ __align__(16) char dsm[];
    __shared__ float sbias[128];

    const int tid = threadIdx.x, lane = tid & 31, wid = tid >> 5;
    const int wm = wid & 3, wn = wid >> 2;
    const int bx = blockIdx.x;
    const int b = bx / 196;
    const int spb = (bx % 196) * 128;

    if (tid < 128) sbias[tid] = bias[tid];

    const int mrow = tid >> 1;
    const int q0 = (tid & 1) * 4;
    int sp_c = spb + mrow;
    int d_c = sp_c / 3136; int r_c = sp_c - d_c*3136; int h_c = r_c / 56, w_c = r_c - h_c*56;
    const int padrow = d_c*PDH + h_c*58 + w_c;
    const __half* XinB = Xin + (size_t)b * PAD_SP * 128;
    const uint32_t sb = smem_u32(dsm);
    const uint32_t dst = sb + (uint32_t)mrow*128u;
    FragCtx f = make_frag_ctx(lane, wm, wn);

    float c[2][8][4];
    #pragma unroll
    for (int t = 0; t < 2; t++)
        #pragma unroll
        for (int j = 0; j < 8; j++)
            #pragma unroll
            for (int q = 0; q < 4; q++) c[t][j][q] = 0.f;

    const int NST = 54;
    auto load_st = [&](int s) {
        int tap = s >> 1, kh64 = (s & 1) * 64;
        int kd = tap / 9; int rem = tap - kd*9; int kh = rem / 3, kw = rem - kh*3;
        int toff = kd*PDH + kh*58 + kw;
        uint32_t base = (uint32_t)(s % 3) * 32768u;
        const __half* ga = XinB + (size_t)(padrow + toff)*128 + kh64;
        const __half* gb = w2 + ((size_t)tap*128 + mrow)*128 + kh64;
        #pragma unroll
        for (int q = q0; q < q0 + 4; q++) {
            uint32_t sw = (uint32_t)((q ^ (mrow & 7)) << 4);
            cp16(dst + base + sw, ga + q*8);
            cp16(dst + base + 16384u + sw, gb + q*8);
        }
    };
    load_st(0); CP_COMMIT();
    load_st(1); CP_COMMIT();
    for (int k = 0; k < NST; k++) {
        CP_WAIT1();
        __syncthreads();
        if (k + 2 < NST) load_st(k + 2);
        CP_COMMIT();
        uint32_t Ab = sb + (uint32_t)(k % 3)*32768u;
        mma_stage(Ab, Ab + 16384u, f, c);
    }
    __syncthreads();

    float* Cb = (float*)dsm;   // 128 x 132
    const int r0 = lane >> 2, c0 = lane & 3;
    #pragma unroll
    for (int t = 0; t < 2; t++) {
        int row = wm*32 + t*16 + r0;
        #pragma unroll
        for (int t2 = 0; t2 < 8; t2++) {
            int col = wn*64 + t2*8 + (c0 << 1);
            float b0s = sbias[col], b1s = sbias[col+1];
            float v0 = c[t][t2][0] + b0s;
            float v1 = c[t][t2][1] + b1s;
            float v2 = c[t][t2][2] + b0s;
            float v3 = c[t][t2][3] + b1s;
            if (leaky) {
                v0 = (v0 >= 0.f) ? v0 : 0.01f*v0;
                v1 = (v1 >= 0.f) ? v1 : 0.01f*v1;
                v2 = (v2 >= 0.f) ? v2 : 0.01f*v2;
                v3 = (v3 >= 0.f) ? v3 : 0.01f*v3;
            }
            Cb[row*132 + col]       = v0;
            Cb[row*132 + col + 1]   = v1;
            Cb[(row+8)*132 + col]   = v2;
            Cb[(row+8)*132 + col+1] = v3;
        }
    }
    __syncthreads();

    if (res) {
        int co = tid >> 1, mh = (tid & 1) << 6;
        const float* rp = res + (size_t)b*256*SP + (size_t)co*SP + spb + mh;
        #pragma unroll
        for (int j4 = 0; j4 < 16; j4++) {
            float4 r4 = *(const float4*)(rp + j4*4);
            Cb[(mh + j4*4 + 0)*132 + co] += r4.x;
            Cb[(mh + j4*4 + 1)*132 + co] += r4.y;
            Cb[(mh + j4*4 + 2)*132 + co] += r4.z;
            Cb[(mh + j4*4 + 3)*132 + co] += r4.w;
        }
        __syncthreads();
    }

    if (outX) {
        int m = tid >> 1, ch = (tid & 1) << 6;
        int sp = spb + m; int d = sp / 3136; int r = sp - d*3136; int h = r / 56, w = r - h*56;
        size_t po = (size_t)(d+1)*PDH + (size_t)(h+1)*58 + (w+1);
        __half* xp = outX + ((size_t)b*PAD_SP + po)*128 + ch;
        #pragma unroll
        for (int j8 = 0; j8 < 8; j8++) {
            const float* p = &Cb[m*132 + ch + j8*8];
            __half2 h0 = __floats2half2_rn(p[0], p[1]);
            __half2 h1 = __floats2half2_rn(p[2], p[3]);
            __half2 h2 = __floats2half2_rn(p[4], p[5]);
            __half2 h3 = __floats2half2_rn(p[6], p[7]);
            uint4 u;
            u.x = *(uint32_t*)&h0; u.y = *(uint32_t*)&h1;
            u.z = *(uint32_t*)&h2; u.w = *(uint32_t*)&h3;
            *(uint4*)(xp + j8*8) = u;
        }
    }
    if (outN) {
        int co = tid >> 1, mh = (tid & 1) << 6;
        float* op = outN + (size_t)b*256*SP + (size_t)co*SP + spb + mh;
        #pragma unroll
        for (int j4 = 0; j4 < 16; j4++) {
            float4 o;
            o.x = Cb[(mh + j4*4 + 0)*132 + co];
            o.y = Cb[(mh + j4*4 + 1)*132 + co];
            o.z = Cb[(mh + j4*4 + 2)*132 + co];
            o.w = Cb[(mh + j4*4 + 3)*132 + co];
            *(float4*)(op + j4*4) = o;
        }
    }
}

// ---------------- launcher ----------------
extern "C" void kernel_launch(void* const* d_in, const int* in_sizes, int n_in,
                              void* d_out, int out_size)
{
    (void)in_sizes; (void)n_in; (void)out_size;
    const float* input  = (const float*)d_in[0];
    const float* n1w    = (const float*)d_in[1];
    const float* n1b    = (const float*)d_in[2];
    const float* n2w    = (const float*)d_in[3];
    const float* n2b    = (const float*)d_in[4];
    const float* wqkv   = (const float*)d_in[5];
    const float* wprojw = (const float*)d_in[6];
    const float* wprojb = (const float*)d_in[7];
    const float* wbias  = (const float*)d_in[8];
    const float* gqkv   = (const float*)d_in[9];
    const float* gprojw = (const float*)d_in[10];
    const float* gprojb = (const float*)d_in[11];
    const float* gbias  = (const float*)d_in[12];
    const float* f1c1w  = (const float*)d_in[13];
    const float* f1c1b  = (const float*)d_in[14];
    const float* f1c2w  = (const float*)d_in[15];
    const float* f1c2b  = (const float*)d_in[16];
    const float* g1c1w  = (const float*)d_in[17];
    const float* g1c1b  = (const float*)d_in[18];
    const float* g1c2w  = (const float*)d_in[19];
    const float* g1c2b  = (const float*)d_in[20];
    float* out = (float*)d_out;

    __half *xh, *qkvh, *atnh, *Xa, *Xb, *w2h, *wqkvh, *gqkvh, *wprjh, *gprjh;
    float *xw, *s, *bmat;
    cudaGetSymbolAddress((void**)&xh,    g_xh);
    cudaGetSymbolAddress((void**)&qkvh,  g_qkvh);
    cudaGetSymbolAddress((void**)&atnh,  g_atnh);
    cudaGetSymbolAddress((void**)&xw,    g_xw);
    cudaGetSymbolAddress((void**)&s,     g_s);
    cudaGetSymbolAddress((void**)&Xa,    g_Xa);
    cudaGetSymbolAddress((void**)&Xb,    g_Xb);
    cudaGetSymbolAddress((void**)&w2h,   g_w2h);
    cudaGetSymbolAddress((void**)&wqkvh, g_wqkvh);
    cudaGetSymbolAddress((void**)&gqkvh, g_gqkvh);
    cudaGetSymbolAddress((void**)&wprjh, g_wprjh);
    cudaGetSymbolAddress((void**)&gprjh, g_gprjh);
    cudaGetSymbolAddress((void**)&bmat,  g_bmat);

    const int TSMEM = 3 * 32768;
    cudaFuncSetAttribute(hgemm_kernel<1>,   cudaFuncAttributeMaxDynamicSharedMemorySize, TSMEM);
    cudaFuncSetAttribute(hgemm_kernel<0>,   cudaFuncAttributeMaxDynamicSharedMemorySize, TSMEM);
    cudaFuncSetAttribute(hgemm_fuse_kernel, cudaFuncAttributeMaxDynamicSharedMemorySize, TSMEM);
    cudaFuncSetAttribute(conv_mma_kernel,   cudaFuncAttributeMaxDynamicSharedMemorySize, TSMEM);

    // all prep in one launch
    prep_kernel<<<9408, 256>>>(wqkv, gqkv, wprojw, gprojw,
                               f1c1w, f1c2w, g1c1w, g1c2w, wbias, gbias,
                               wqkvh, gqkvh, wprjh, gprjh, w2h, bmat);

    // window attention block
    ln_in_kernel<<<1792, 256>>>(input, n1w, n1b, xh);
    hgemm_kernel<1><<<dim3(6, 392), 256, TSMEM>>>(xh, wqkvh, nullptr, nullptr, qkvh, 768);
    attn_mma_kernel<<<dim3(512, 4), 256>>>(qkvh, bmat, atnh, 0);
    hgemm_kernel<0><<<dim3(2, 392), 256, TSMEM>>>(atnh, wprjh, wprojb, nullptr, xw, 256);
    // grid attention block (proj fused with residuals -> s, Xa)
    ln_row_kernel<<<6272, 256>>>(xw, n2w, n2b, xh);
    hgemm_kernel<1><<<dim3(6, 392), 256, TSMEM>>>(xh, gqkvh, nullptr, nullptr, qkvh, 768);
    attn_mma_kernel<<<dim3(512, 4), 256>>>(qkvh, bmat + (size_t)4*128*112, atnh, 1);
    hgemm_fuse_kernel<<<dim3(2, 392), 256, TSMEM>>>(atnh, gprjh, gprojb, xw, input, s, Xa);

    // conv chain
    conv_mma_kernel<<<392, 256, TSMEM>>>(Xa, w2h,            f1c1b, nullptr, nullptr, Xb, 1);
    conv_mma_kernel<<<392, 256, TSMEM>>>(Xb, w2h + W2SZ,     f1c2b, s, out, Xa, 0);
    conv_mma_kernel<<<392, 256, TSMEM>>>(Xa, w2h + 2*W2SZ,   g1c1b, nullptr, nullptr, Xb, 1);
    conv_mma_kernel<<<392, 256, TSMEM>>>(Xb, w2h + 3*W2SZ,   g1c2b, s + (size_t)128*SP,
                                         out + (size_t)128*SP, nullptr, 0);
}